// round 13
// baseline (speedup 1.0000x reference)
#include <cuda_runtime.h>
#include <math.h>

#define Nn 10000
#define Ee 160000
#define Etot (Ee + Nn)
#define Hh 7
#define Cc 64
#define HC 448

// ---------------- scratch ----------------
__device__ float g_h0[Nn * 512];
__device__ float g_h1[Nn * 256];
__device__ float g_hA[Nn * 64];
__device__ float g_hB[Nn * 64];
__device__ float g_xl[Nn * HC];
__device__ float g_xr[Nn * HC];
__device__ int   g_deg[Nn];
__device__ int   g_rowptr[Nn + 1];
__device__ int   g_wpos[Nn];
__device__ int   g_csr_src[Etot];
__device__ int   g_is64;

// ---------------- edge dtype detection (parallel) ----------------
__global__ void k_detect(const int* __restrict__ ei32) {
    int nz = (ei32[2 * threadIdx.x + 1] != 0) ? 1 : 0;
    int tot = __syncthreads_count(nz);
    if (threadIdx.x == 0) g_is64 = (tot == 0) ? 1 : 0;
}
__device__ __forceinline__ int edge_val(const void* ei, int idx) {
    if (g_is64) return (int)((const long long*)ei)[idx];
    return ((const int*)ei)[idx];
}

// ---------------- CSR build ----------------
__global__ void k_clear_deg() {
    int i = blockIdx.x * blockDim.x + threadIdx.x;
    if (i < Nn) g_deg[i] = 0;
}
__global__ void k_count(const void* __restrict__ ei) {
    int e = blockIdx.x * blockDim.x + threadIdx.x;
    if (e >= Etot) return;
    int dst = (e < Ee) ? edge_val(ei, Ee + e) : (e - Ee);
    if ((unsigned)dst < Nn) atomicAdd(&g_deg[dst], 1);
}

__global__ void k_scan() {
    int t = threadIdx.x;
    int base = t * 10;
    int v[10]; int s = 0;
#pragma unroll
    for (int i = 0; i < 10; i++) {
        int idx = base + i;
        v[i] = (idx < Nn) ? g_deg[idx] : 0;
        s += v[i];
    }
    int lane = t & 31, wid = t >> 5;
    int ss = s;
#pragma unroll
    for (int o = 1; o < 32; o <<= 1) {
        int u = __shfl_up_sync(0xFFFFFFFFu, ss, o);
        if (lane >= o) ss += u;
    }
    __shared__ int wsum[32];
    if (lane == 31) wsum[wid] = ss;
    __syncthreads();
    if (wid == 0) {
        int w = wsum[lane];
#pragma unroll
        for (int o = 1; o < 32; o <<= 1) {
            int u = __shfl_up_sync(0xFFFFFFFFu, w, o);
            if (lane >= o) w += u;
        }
        wsum[lane] = w;
    }
    __syncthreads();
    int excl = ss - s + (wid ? wsum[wid - 1] : 0);
    int run = excl;
#pragma unroll
    for (int i = 0; i < 10; i++) {
        int idx = base + i;
        if (idx < Nn) {
            g_wpos[idx] = run;
            run += v[i];
            g_rowptr[idx + 1] = run;
        }
    }
    if (t == 0) g_rowptr[0] = 0;
}

__global__ void k_scatter(const void* __restrict__ ei) {
    int e = blockIdx.x * blockDim.x + threadIdx.x;
    if (e >= Etot) return;
    int src, dst;
    if (e < Ee) { src = edge_val(ei, e); dst = edge_val(ei, Ee + e); }
    else        { src = dst = e - Ee; }
    if ((unsigned)dst >= Nn || (unsigned)src >= Nn) return;
    int pos = atomicAdd(&g_wpos[dst], 1);
    if ((unsigned)pos < Etot) g_csr_src[pos] = src;
}

// ---------------- bf16x3 helpers ----------------
__device__ __forceinline__ unsigned pack_bf16(float f_even, float f_odd) {
    unsigned r;
    asm("cvt.rn.bf16x2.f32 %0, %1, %2;" : "=r"(r) : "f"(f_odd), "f"(f_even));
    return r;
}
__device__ __forceinline__ void split2(float f0, float f1, unsigned& hi, unsigned& lo) {
    hi = pack_bf16(f0, f1);
    float r0 = f0 - __uint_as_float(hi << 16);
    float r1 = f1 - __uint_as_float(hi & 0xFFFF0000u);
    lo = pack_bf16(r0, r1);
}
__device__ __forceinline__ void mma16(float c[4], const unsigned a[4], const unsigned b[2]) {
    asm("mma.sync.aligned.m16n8k16.row.col.f32.bf16.bf16.f32 "
        "{%0,%1,%2,%3},{%4,%5,%6,%7},{%8,%9},{%0,%1,%2,%3};"
        : "+f"(c[0]), "+f"(c[1]), "+f"(c[2]), "+f"(c[3])
        : "r"(a[0]), "r"(a[1]), "r"(a[2]), "r"(a[3]), "r"(b[0]), "r"(b[1]));
}

// ---------------- BN=64 GEMM, double-buffered smem (W3 + layers) ----------------
__global__ __launch_bounds__(256) void k_bf16gemm(
    const float* __restrict__ A,
    const float* __restrict__ B0, const float* __restrict__ bias0, float* __restrict__ C0,
    const float* __restrict__ B1, const float* __restrict__ bias1, float* __restrict__ C1,
    int M, int N, int K, int doRelu)
{
    const float* B    = (blockIdx.z == 0) ? B0 : B1;
    const float* bias = (blockIdx.z == 0) ? bias0 : bias1;
    float*       C    = (blockIdx.z == 0) ? C0 : C1;

    __shared__ unsigned As_hi[2][128][9], As_lo[2][128][9];
    __shared__ unsigned Bs_hi[2][64][9],  Bs_lo[2][64][9];

    int tid = threadIdx.x;
    int lane = tid & 31, warp = tid >> 5;
    int warpM = warp & 3, warpN = warp >> 2;
    int rowBase = blockIdx.y * 128;
    int colBase = blockIdx.x * 64;
    int lm = lane >> 2, lk = lane & 3;

    float acc[2][4][4];
#pragma unroll
    for (int mt = 0; mt < 2; mt++)
#pragma unroll
        for (int nt = 0; nt < 4; nt++)
#pragma unroll
            for (int i = 0; i < 4; i++) acc[mt][nt][i] = 0.f;

    int aRow = tid >> 2;
    int aCol = (tid & 3) * 4;
    int bKp  = tid >> 5;
    int bCol = (tid & 31) * 2;
    int gr0 = rowBase + aRow, gr1 = rowBase + 64 + aRow;

    int kIters = K >> 4;
    float4 aR0, aR1; float2 bR0, bR1;

    aR0 = (gr0 < M) ? *(const float4*)(A + (size_t)gr0 * K + aCol) : make_float4(0, 0, 0, 0);
    aR1 = (gr1 < M) ? *(const float4*)(A + (size_t)gr1 * K + aCol) : make_float4(0, 0, 0, 0);
    bR0 = *(const float2*)(B + (size_t)(bKp * 2)     * N + colBase + bCol);
    bR1 = *(const float2*)(B + (size_t)(bKp * 2 + 1) * N + colBase + bCol);
    {
        unsigned h, l;
        split2(aR0.x, aR0.y, h, l); As_hi[0][aRow][aCol / 2] = h;     As_lo[0][aRow][aCol / 2] = l;
        split2(aR0.z, aR0.w, h, l); As_hi[0][aRow][aCol / 2 + 1] = h; As_lo[0][aRow][aCol / 2 + 1] = l;
        split2(aR1.x, aR1.y, h, l); As_hi[0][64 + aRow][aCol / 2] = h;     As_lo[0][64 + aRow][aCol / 2] = l;
        split2(aR1.z, aR1.w, h, l); As_hi[0][64 + aRow][aCol / 2 + 1] = h; As_lo[0][64 + aRow][aCol / 2 + 1] = l;
        split2(bR0.x, bR1.x, h, l); Bs_hi[0][bCol][bKp] = h;     Bs_lo[0][bCol][bKp] = l;
        split2(bR0.y, bR1.y, h, l); Bs_hi[0][bCol + 1][bKp] = h; Bs_lo[0][bCol + 1][bKp] = l;
    }
    __syncthreads();

    for (int it = 0; it < kIters; it++) {
        int cb = it & 1, nb = cb ^ 1;
        if (it + 1 < kIters) {
            int k0 = (it + 1) * 16;
            aR0 = (gr0 < M) ? *(const float4*)(A + (size_t)gr0 * K + k0 + aCol) : make_float4(0, 0, 0, 0);
            aR1 = (gr1 < M) ? *(const float4*)(A + (size_t)gr1 * K + k0 + aCol) : make_float4(0, 0, 0, 0);
            bR0 = *(const float2*)(B + (size_t)(k0 + bKp * 2)     * N + colBase + bCol);
            bR1 = *(const float2*)(B + (size_t)(k0 + bKp * 2 + 1) * N + colBase + bCol);
        }

        unsigned ah[2][4], al[2][4], bh[4][2], bl[4][2];
#pragma unroll
        for (int mt = 0; mt < 2; mt++) {
            int rm = warpM * 32 + mt * 16 + lm;
            ah[mt][0] = As_hi[cb][rm][lk];     al[mt][0] = As_lo[cb][rm][lk];
            ah[mt][1] = As_hi[cb][rm + 8][lk]; al[mt][1] = As_lo[cb][rm + 8][lk];
            ah[mt][2] = As_hi[cb][rm][lk + 4];     al[mt][2] = As_lo[cb][rm][lk + 4];
            ah[mt][3] = As_hi[cb][rm + 8][lk + 4]; al[mt][3] = As_lo[cb][rm + 8][lk + 4];
        }
#pragma unroll
        for (int nt = 0; nt < 4; nt++) {
            int cn = warpN * 32 + nt * 8 + lm;
            bh[nt][0] = Bs_hi[cb][cn][lk];     bl[nt][0] = Bs_lo[cb][cn][lk];
            bh[nt][1] = Bs_hi[cb][cn][lk + 4]; bl[nt][1] = Bs_lo[cb][cn][lk + 4];
        }
#pragma unroll
        for (int mt = 0; mt < 2; mt++)
#pragma unroll
            for (int nt = 0; nt < 4; nt++) {
                mma16(acc[mt][nt], ah[mt], bl[nt]);
                mma16(acc[mt][nt], al[mt], bh[nt]);
                mma16(acc[mt][nt], ah[mt], bh[nt]);
            }

        if (it + 1 < kIters) {
            unsigned h, l;
            split2(aR0.x, aR0.y, h, l); As_hi[nb][aRow][aCol / 2] = h;     As_lo[nb][aRow][aCol / 2] = l;
            split2(aR0.z, aR0.w, h, l); As_hi[nb][aRow][aCol / 2 + 1] = h; As_lo[nb][aRow][aCol / 2 + 1] = l;
            split2(aR1.x, aR1.y, h, l); As_hi[nb][64 + aRow][aCol / 2] = h;     As_lo[nb][64 + aRow][aCol / 2] = l;
            split2(aR1.z, aR1.w, h, l); As_hi[nb][64 + aRow][aCol / 2 + 1] = h; As_lo[nb][64 + aRow][aCol / 2 + 1] = l;
            split2(bR0.x, bR1.x, h, l); Bs_hi[nb][bCol][bKp] = h;     Bs_lo[nb][bCol][bKp] = l;
            split2(bR0.y, bR1.y, h, l); Bs_hi[nb][bCol + 1][bKp] = h; Bs_lo[nb][bCol + 1][bKp] = l;
            __syncthreads();
        }
    }

#pragma unroll
    for (int mt = 0; mt < 2; mt++) {
        int r0 = rowBase + warpM * 32 + mt * 16 + lm;
#pragma unroll
        for (int nt = 0; nt < 4; nt++) {
            int col = colBase + warpN * 32 + nt * 8 + lk * 2;
            float bb0 = bias ? bias[col] : 0.f;
            float bb1 = bias ? bias[col + 1] : 0.f;
            float v0 = acc[mt][nt][0] + bb0, v1 = acc[mt][nt][1] + bb1;
            float v2 = acc[mt][nt][2] + bb0, v3 = acc[mt][nt][3] + bb1;
            if (doRelu) {
                v0 = fmaxf(v0, 0.f); v1 = fmaxf(v1, 0.f);
                v2 = fmaxf(v2, 0.f); v3 = fmaxf(v3, 0.f);
            }
            if (r0 < M)     *(float2*)(C + (size_t)r0 * N + col)       = make_float2(v0, v1);
            if (r0 + 8 < M) *(float2*)(C + (size_t)(r0 + 8) * N + col) = make_float2(v2, v3);
        }
    }
}

// ---------------- BN=128 GEMM, warp tile 64x32, double-buffered (W1/W2) ----------------
__global__ __launch_bounds__(256) void k_gemm128(
    const float* __restrict__ A, const float* __restrict__ B,
    const float* __restrict__ bias, float* __restrict__ C,
    int M, int N, int K, int doRelu)
{
    __shared__ unsigned As_hi[2][128][9], As_lo[2][128][9];
    __shared__ unsigned Bs_hi[2][128][9], Bs_lo[2][128][9];

    int tid = threadIdx.x;
    int lane = tid & 31, warp = tid >> 5;
    int warpM = warp >> 2;
    int warpN = warp & 3;
    int rowBase = blockIdx.y * 128;
    int colBase = blockIdx.x * 128;
    int lm = lane >> 2, lk = lane & 3;

    float acc[4][4][4];
#pragma unroll
    for (int mt = 0; mt < 4; mt++)
#pragma unroll
        for (int nt = 0; nt < 4; nt++)
#pragma unroll
            for (int i = 0; i < 4; i++) acc[mt][nt][i] = 0.f;

    int aRow = tid >> 2;
    int aCol = (tid & 3) * 4;
    int bKp  = tid >> 6;
    int bCol = (tid & 63) * 2;
    int gr0 = rowBase + aRow, gr1 = rowBase + 64 + aRow;

    int kIters = K >> 4;
    float4 aR0, aR1;
    float2 bA0, bA1, bB0, bB1;

    aR0 = (gr0 < M) ? *(const float4*)(A + (size_t)gr0 * K + aCol) : make_float4(0, 0, 0, 0);
    aR1 = (gr1 < M) ? *(const float4*)(A + (size_t)gr1 * K + aCol) : make_float4(0, 0, 0, 0);
    {
        const float* bp = B + colBase + bCol;
        bA0 = *(const float2*)(bp + (size_t)(bKp * 2) * N);
        bA1 = *(const float2*)(bp + (size_t)(bKp * 2 + 1) * N);
        bB0 = *(const float2*)(bp + (size_t)((bKp + 4) * 2) * N);
        bB1 = *(const float2*)(bp + (size_t)((bKp + 4) * 2 + 1) * N);
    }
    {
        unsigned h, l;
        split2(aR0.x, aR0.y, h, l); As_hi[0][aRow][aCol / 2] = h;     As_lo[0][aRow][aCol / 2] = l;
        split2(aR0.z, aR0.w, h, l); As_hi[0][aRow][aCol / 2 + 1] = h; As_lo[0][aRow][aCol / 2 + 1] = l;
        split2(aR1.x, aR1.y, h, l); As_hi[0][64 + aRow][aCol / 2] = h;     As_lo[0][64 + aRow][aCol / 2] = l;
        split2(aR1.z, aR1.w, h, l); As_hi[0][64 + aRow][aCol / 2 + 1] = h; As_lo[0][64 + aRow][aCol / 2 + 1] = l;
        split2(bA0.x, bA1.x, h, l); Bs_hi[0][bCol][bKp] = h;     Bs_lo[0][bCol][bKp] = l;
        split2(bA0.y, bA1.y, h, l); Bs_hi[0][bCol + 1][bKp] = h; Bs_lo[0][bCol + 1][bKp] = l;
        split2(bB0.x, bB1.x, h, l); Bs_hi[0][bCol][bKp + 4] = h;     Bs_lo[0][bCol][bKp + 4] = l;
        split2(bB0.y, bB1.y, h, l); Bs_hi[0][bCol + 1][bKp + 4] = h; Bs_lo[0][bCol + 1][bKp + 4] = l;
    }
    __syncthreads();

    for (int it = 0; it < kIters; it++) {
        int cb = it & 1, nb = cb ^ 1;
        if (it + 1 < kIters) {
            int k0 = (it + 1) * 16;
            aR0 = (gr0 < M) ? *(const float4*)(A + (size_t)gr0 * K + k0 + aCol) : make_float4(0, 0, 0, 0);
            aR1 = (gr1 < M) ? *(const float4*)(A + (size_t)gr1 * K + k0 + aCol) : make_float4(0, 0, 0, 0);
            const float* bp = B + colBase + bCol;
            bA0 = *(const float2*)(bp + (size_t)(k0 + bKp * 2) * N);
            bA1 = *(const float2*)(bp + (size_t)(k0 + bKp * 2 + 1) * N);
            bB0 = *(const float2*)(bp + (size_t)(k0 + (bKp + 4) * 2) * N);
            bB1 = *(const float2*)(bp + (size_t)(k0 + (bKp + 4) * 2 + 1) * N);
        }

        unsigned ah[4][4], al[4][4], bh[4][2], bl[4][2];
#pragma unroll
        for (int mt = 0; mt < 4; mt++) {
            int rm = warpM * 64 + mt * 16 + lm;
            ah[mt][0] = As_hi[cb][rm][lk];     al[mt][0] = As_lo[cb][rm][lk];
            ah[mt][1] = As_hi[cb][rm + 8][lk]; al[mt][1] = As_lo[cb][rm + 8][lk];
            ah[mt][2] = As_hi[cb][rm][lk + 4];     al[mt][2] = As_lo[cb][rm][lk + 4];
            ah[mt][3] = As_hi[cb][rm + 8][lk + 4]; al[mt][3] = As_lo[cb][rm + 8][lk + 4];
        }
#pragma unroll
        for (int nt = 0; nt < 4; nt++) {
            int cn = warpN * 32 + nt * 8 + lm;
            bh[nt][0] = Bs_hi[cb][cn][lk];     bl[nt][0] = Bs_lo[cb][cn][lk];
            bh[nt][1] = Bs_hi[cb][cn][lk + 4]; bl[nt][1] = Bs_lo[cb][cn][lk + 4];
        }
#pragma unroll
        for (int mt = 0; mt < 4; mt++)
#pragma unroll
            for (int nt = 0; nt < 4; nt++) {
                mma16(acc[mt][nt], ah[mt], bl[nt]);
                mma16(acc[mt][nt], al[mt], bh[nt]);
                mma16(acc[mt][nt], ah[mt], bh[nt]);
            }

        if (it + 1 < kIters) {
            unsigned h, l;
            split2(aR0.x, aR0.y, h, l); As_hi[nb][aRow][aCol / 2] = h;     As_lo[nb][aRow][aCol / 2] = l;
            split2(aR0.z, aR0.w, h, l); As_hi[nb][aRow][aCol / 2 + 1] = h; As_lo[nb][aRow][aCol / 2 + 1] = l;
            split2(aR1.x, aR1.y, h, l); As_hi[nb][64 + aRow][aCol / 2] = h;     As_lo[nb][64 + aRow][aCol / 2] = l;
            split2(aR1.z, aR1.w, h, l); As_hi[nb][64 + aRow][aCol / 2 + 1] = h; As_lo[nb][64 + aRow][aCol / 2 + 1] = l;
            split2(bA0.x, bA1.x, h, l); Bs_hi[nb][bCol][bKp] = h;     Bs_lo[nb][bCol][bKp] = l;
            split2(bA0.y, bA1.y, h, l); Bs_hi[nb][bCol + 1][bKp] = h; Bs_lo[nb][bCol + 1][bKp] = l;
            split2(bB0.x, bB1.x, h, l); Bs_hi[nb][bCol][bKp + 4] = h;     Bs_lo[nb][bCol][bKp + 4] = l;
            split2(bB0.y, bB1.y, h, l); Bs_hi[nb][bCol + 1][bKp + 4] = h; Bs_lo[nb][bCol + 1][bKp + 4] = l;
            __syncthreads();
        }
    }

#pragma unroll
    for (int mt = 0; mt < 4; mt++) {
        int r0 = rowBase + warpM * 64 + mt * 16 + lm;
#pragma unroll
        for (int nt = 0; nt < 4; nt++) {
            int col = colBase + warpN * 32 + nt * 8 + lk * 2;
            float bb0 = bias ? bias[col] : 0.f;
            float bb1 = bias ? bias[col + 1] : 0.f;
            float v0 = acc[mt][nt][0] + bb0, v1 = acc[mt][nt][1] + bb1;
            float v2 = acc[mt][nt][2] + bb0, v3 = acc[mt][nt][3] + bb1;
            if (doRelu) {
                v0 = fmaxf(v0, 0.f); v1 = fmaxf(v1, 0.f);
                v2 = fmaxf(v2, 0.f); v3 = fmaxf(v3, 0.f);
            }
            if (r0 < M)     *(float2*)(C + (size_t)r0 * N + col)       = make_float2(v0, v1);
            if (r0 + 8 < M) *(float2*)(C + (size_t)(r0 + 8) * N + col) = make_float2(v2, v3);
        }
    }
}

// ---------------- per-dst GATv2 aggregation (warp-prefetched srcs, 4-way ILP) ----------------
// Warp h owns head h; lane owns channels (2*lane, 2*lane+1) as one float2.
// src indices for up to 32 edges fetched with ONE coalesced load and broadcast
// via shfl, removing the csr->xl pointer chase; 4 edges processed with
// interleaved loads + interleaved shfl reduction trees.
__global__ __launch_bounds__(256) void k_gat_dst(
    const float* __restrict__ xl, const float* __restrict__ xr,
    const float* __restrict__ att, const float* __restrict__ cbias,
    float* __restrict__ hout)
{
    __shared__ float sh_out[Hh][Cc];

    int dst = blockIdx.x;
    int tid = threadIdx.x;
    int wid = tid >> 5, lane = tid & 31;

    if (wid < Hh) {
        int h = wid;
        float2 av = *(const float2*)(att + h * Cc + 2 * lane);
        float2 rv = *(const float2*)(xr + (size_t)dst * HC + h * Cc + 2 * lane);

        float s = 0.f, a0 = 0.f, a1 = 0.f;
        int beg = g_rowptr[dst], end = g_rowptr[dst + 1];

        for (int base = beg; base < end; base += 32) {
            int idx = base + lane;
            int mysrc = (idx < end) ? g_csr_src[idx] : 0;
            int cnt = min(32, end - base);
            int j = 0;
            for (; j + 4 <= cnt; j += 4) {
                int s0 = __shfl_sync(0xFFFFFFFFu, mysrc, j);
                int s1 = __shfl_sync(0xFFFFFFFFu, mysrc, j + 1);
                int s2 = __shfl_sync(0xFFFFFFFFu, mysrc, j + 2);
                int s3 = __shfl_sync(0xFFFFFFFFu, mysrc, j + 3);
                float2 xv0 = *(const float2*)(xl + (size_t)s0 * HC + h * Cc + 2 * lane);
                float2 xv1 = *(const float2*)(xl + (size_t)s1 * HC + h * Cc + 2 * lane);
                float2 xv2 = *(const float2*)(xl + (size_t)s2 * HC + h * Cc + 2 * lane);
                float2 xv3 = *(const float2*)(xl + (size_t)s3 * HC + h * Cc + 2 * lane);
                float p0, p1, p2, p3;
                {
                    float v0 = xv0.x + rv.x; v0 = (v0 > 0.f) ? v0 : 0.2f * v0;
                    float v1 = xv0.y + rv.y; v1 = (v1 > 0.f) ? v1 : 0.2f * v1;
                    p0 = v0 * av.x + v1 * av.y;
                }
                {
                    float v0 = xv1.x + rv.x; v0 = (v0 > 0.f) ? v0 : 0.2f * v0;
                    float v1 = xv1.y + rv.y; v1 = (v1 > 0.f) ? v1 : 0.2f * v1;
                    p1 = v0 * av.x + v1 * av.y;
                }
                {
                    float v0 = xv2.x + rv.x; v0 = (v0 > 0.f) ? v0 : 0.2f * v0;
                    float v1 = xv2.y + rv.y; v1 = (v1 > 0.f) ? v1 : 0.2f * v1;
                    p2 = v0 * av.x + v1 * av.y;
                }
                {
                    float v0 = xv3.x + rv.x; v0 = (v0 > 0.f) ? v0 : 0.2f * v0;
                    float v1 = xv3.y + rv.y; v1 = (v1 > 0.f) ? v1 : 0.2f * v1;
                    p3 = v0 * av.x + v1 * av.y;
                }
#pragma unroll
                for (int o = 16; o; o >>= 1) {
                    p0 += __shfl_xor_sync(0xFFFFFFFFu, p0, o);
                    p1 += __shfl_xor_sync(0xFFFFFFFFu, p1, o);
                    p2 += __shfl_xor_sync(0xFFFFFFFFu, p2, o);
                    p3 += __shfl_xor_sync(0xFFFFFFFFu, p3, o);
                }
                float w0 = __expf(p0), w1 = __expf(p1), w2 = __expf(p2), w3 = __expf(p3);
                s  += (w0 + w1) + (w2 + w3);
                a0 += w0 * xv0.x + w1 * xv1.x + w2 * xv2.x + w3 * xv3.x;
                a1 += w0 * xv0.y + w1 * xv1.y + w2 * xv2.y + w3 * xv3.y;
            }
            for (; j < cnt; j++) {
                int s0 = __shfl_sync(0xFFFFFFFFu, mysrc, j);
                float2 xv = *(const float2*)(xl + (size_t)s0 * HC + h * Cc + 2 * lane);
                float v0 = xv.x + rv.x; v0 = (v0 > 0.f) ? v0 : 0.2f * v0;
                float v1 = xv.y + rv.y; v1 = (v1 > 0.f) ? v1 : 0.2f * v1;
                float p = v0 * av.x + v1 * av.y;
#pragma unroll
                for (int o = 16; o; o >>= 1) p += __shfl_xor_sync(0xFFFFFFFFu, p, o);
                float w = __expf(p);
                s  += w;
                a0 += w * xv.x;
                a1 += w * xv.y;
            }
        }
        float inv = 1.f / (s + 1e-16f);
        sh_out[h][2 * lane]     = a0 * inv;
        sh_out[h][2 * lane + 1] = a1 * inv;
    }
    __syncthreads();

    if (tid < Cc) {
        float v = 0.f;
#pragma unroll
        for (int h = 0; h < Hh; h++) v += sh_out[h][tid];
        v = v * (1.f / 7.f) + cbias[tid];
        hout[(size_t)dst * Cc + tid] = fmaxf(v, 0.f);
    }
}

// ---------------- fused output MLP + log_softmax ----------------
__global__ __launch_bounds__(128) void k_outmlp(
    const float* __restrict__ h,
    const float* __restrict__ V1, const float* __restrict__ c1,
    const float* __restrict__ V2, const float* __restrict__ c2,
    const float* __restrict__ V3, const float* __restrict__ c3,
    float* __restrict__ out)
{
    __shared__ float sV1[64 * 32], sV2[32 * 16], sV3[16 * 9];
    __shared__ float sc1[32], sc2[16], sc3[9];
    int tid = threadIdx.x;
    for (int i = tid; i < 64 * 32; i += 128) sV1[i] = V1[i];
    for (int i = tid; i < 32 * 16; i += 128) sV2[i] = V2[i];
    for (int i = tid; i < 16 * 9; i += 128)  sV3[i] = V3[i];
    if (tid < 32) sc1[tid] = c1[tid];
    if (tid < 16) sc2[tid] = c2[tid];
    if (tid < 9)  sc3[tid] = c3[tid];
    __syncthreads();

    int row = blockIdx.x * 128 + tid;
    if (row >= Nn) return;

    float x[64];
#pragma unroll
    for (int k = 0; k < 64; k++) x[k] = fmaxf(h[(size_t)row * 64 + k], 0.f);

    float t1[32];
#pragma unroll
    for (int j = 0; j < 32; j++) {
        float v = sc1[j];
#pragma unroll
        for (int k = 0; k < 64; k++) v += x[k] * sV1[k * 32 + j];
        t1[j] = fmaxf(v, 0.f);
    }
    float t2[16];
#pragma unroll
    for (int j = 0; j < 16; j++) {
        float v = sc2[j];
#pragma unroll
        for (int k = 0; k < 32; k++) v += t1[k] * sV2[k * 16 + j];
        t2[j] = fmaxf(v, 0.f);
    }
    float t3[9];
    float mx = -INFINITY;
#pragma unroll
    for (int j = 0; j < 9; j++) {
        float v = sc3[j];
#pragma unroll
        for (int k = 0; k < 16; k++) v += t2[k] * sV3[k * 9 + j];
        t3[j] = v;
        mx = fmaxf(mx, v);
    }
    float se = 0.f;
#pragma unroll
    for (int j = 0; j < 9; j++) se += expf(t3[j] - mx);
    float lse = logf(se) + mx;
#pragma unroll
    for (int j = 0; j < 9; j++) out[(size_t)row * 9 + j] = t3[j] - lse;
}

// ---------------- host ----------------
static void launch_gemm64(const float* A, const float* B, const float* bias,
                          float* C, int M, int N, int K, int relu)
{
    dim3 grid(N / 64, (M + 127) / 128, 1);
    k_bf16gemm<<<grid, 256>>>(A, B, bias, C, B, bias, C, M, N, K, relu);
}
static void launch_gemm128(const float* A, const float* B, const float* bias,
                           float* C, int M, int N, int K, int relu)
{
    dim3 grid(N / 128, (M + 127) / 128, 1);
    k_gemm128<<<grid, 256>>>(A, B, bias, C, M, N, K, relu);
}

extern "C" void kernel_launch(void* const* d_in, const int* in_sizes, int n_in,
                              void* d_out, int out_size)
{
    const float* x  = (const float*)d_in[0];
    const void*  ei = d_in[1];
    const float* W1 = (const float*)d_in[2];  const float* b1 = (const float*)d_in[3];
    const float* W2 = (const float*)d_in[4];  const float* b2 = (const float*)d_in[5];
    const float* W3 = (const float*)d_in[6];  const float* b3 = (const float*)d_in[7];
    const float* Wl = (const float*)d_in[8];  const float* bl = (const float*)d_in[9];
    const float* Wr = (const float*)d_in[10];
    const float* att   = (const float*)d_in[11];
    const float* cbias = (const float*)d_in[12];
    const float* V1 = (const float*)d_in[13]; const float* c1 = (const float*)d_in[14];
    const float* V2 = (const float*)d_in[15]; const float* c2 = (const float*)d_in[16];
    const float* V3 = (const float*)d_in[17]; const float* c3 = (const float*)d_in[18];
    float* out = (float*)d_out;

    float *p_h0, *p_h1, *p_hA, *p_hB, *p_xl, *p_xr;
    cudaGetSymbolAddress((void**)&p_h0, g_h0);
    cudaGetSymbolAddress((void**)&p_h1, g_h1);
    cudaGetSymbolAddress((void**)&p_hA, g_hA);
    cudaGetSymbolAddress((void**)&p_hB, g_hB);
    cudaGetSymbolAddress((void**)&p_xl, g_xl);
    cudaGetSymbolAddress((void**)&p_xr, g_xr);

    k_detect<<<1, 256>>>((const int*)ei);
    k_clear_deg<<<(Nn + 255) / 256, 256>>>();
    k_count<<<(Etot + 255) / 256, 256>>>(ei);
    launch_gemm128(x, W1, b1, p_h0, Nn, 512, 1024, 1);   // independent of CSR
    k_scan<<<1, 1024>>>();
    k_scatter<<<(Etot + 255) / 256, 256>>>(ei);

    launch_gemm128(p_h0, W2, b2, p_h1, Nn, 256, 512, 1);
    launch_gemm64(p_h1, W3, b3, p_hA, Nn, 64, 256, 1);

    float* cur = p_hA;
    float* nxt = p_hB;
    for (int l = 0; l < 5; l++) {
        const float* Wl_l = Wl + (size_t)l * 64 * HC;
        const float* bl_l = bl + (size_t)l * HC;
        const float* Wr_l = Wr + (size_t)l * 64 * HC;
        const float* att_l = att + (size_t)l * Hh * Cc;
        const float* cb_l  = cbias + (size_t)l * Cc;
        dim3 grid(HC / 64, (Nn + 127) / 128, 2);
        k_bf16gemm<<<grid, 256>>>(cur, Wl_l, bl_l, p_xl, Wr_l, nullptr, p_xr,
                                  Nn, HC, 64, 0);
        k_gat_dst<<<Nn, 256>>>(p_xl, p_xr, att_l, cb_l, nxt);
        float* t = cur; cur = nxt; nxt = t;
    }

    k_outmlp<<<(Nn + 127) / 128, 128>>>(cur, V1, c1, V2, c2, V3, c3, out);
}

// round 14
// speedup vs baseline: 1.0891x; 1.0891x over previous
#include <cuda_runtime.h>
#include <math.h>

#define Nn 10000
#define Ee 160000
#define Etot (Ee + Nn)
#define Hh 7
#define Cc 64
#define HC 448

// ---------------- scratch ----------------
__device__ float g_h0[Nn * 512];
__device__ float g_h1[Nn * 256];
__device__ float g_hA[Nn * 64];
__device__ float g_hB[Nn * 64];
__device__ float g_xl[Nn * HC];
__device__ float g_xr[Nn * HC];
__device__ int   g_deg[Nn];
__device__ int   g_rowptr[Nn + 1];
__device__ int   g_wpos[Nn];
__device__ int   g_csr_src[Etot];
__device__ int   g_is64;

// ---------------- edge dtype detection (parallel) ----------------
__global__ void k_detect(const int* __restrict__ ei32) {
    int nz = (ei32[2 * threadIdx.x + 1] != 0) ? 1 : 0;
    int tot = __syncthreads_count(nz);
    if (threadIdx.x == 0) g_is64 = (tot == 0) ? 1 : 0;
}
__device__ __forceinline__ int edge_val(const void* ei, int idx) {
    if (g_is64) return (int)((const long long*)ei)[idx];
    return ((const int*)ei)[idx];
}

// ---------------- CSR build ----------------
__global__ void k_clear_deg() {
    int i = blockIdx.x * blockDim.x + threadIdx.x;
    if (i < Nn) g_deg[i] = 0;
}
__global__ void k_count(const void* __restrict__ ei) {
    int e = blockIdx.x * blockDim.x + threadIdx.x;
    if (e >= Etot) return;
    int dst = (e < Ee) ? edge_val(ei, Ee + e) : (e - Ee);
    if ((unsigned)dst < Nn) atomicAdd(&g_deg[dst], 1);
}

__global__ void k_scan() {
    int t = threadIdx.x;
    int base = t * 10;
    int v[10]; int s = 0;
#pragma unroll
    for (int i = 0; i < 10; i++) {
        int idx = base + i;
        v[i] = (idx < Nn) ? g_deg[idx] : 0;
        s += v[i];
    }
    int lane = t & 31, wid = t >> 5;
    int ss = s;
#pragma unroll
    for (int o = 1; o < 32; o <<= 1) {
        int u = __shfl_up_sync(0xFFFFFFFFu, ss, o);
        if (lane >= o) ss += u;
    }
    __shared__ int wsum[32];
    if (lane == 31) wsum[wid] = ss;
    __syncthreads();
    if (wid == 0) {
        int w = wsum[lane];
#pragma unroll
        for (int o = 1; o < 32; o <<= 1) {
            int u = __shfl_up_sync(0xFFFFFFFFu, w, o);
            if (lane >= o) w += u;
        }
        wsum[lane] = w;
    }
    __syncthreads();
    int excl = ss - s + (wid ? wsum[wid - 1] : 0);
    int run = excl;
#pragma unroll
    for (int i = 0; i < 10; i++) {
        int idx = base + i;
        if (idx < Nn) {
            g_wpos[idx] = run;
            run += v[i];
            g_rowptr[idx + 1] = run;
        }
    }
    if (t == 0) g_rowptr[0] = 0;
}

__global__ void k_scatter(const void* __restrict__ ei) {
    int e = blockIdx.x * blockDim.x + threadIdx.x;
    if (e >= Etot) return;
    int src, dst;
    if (e < Ee) { src = edge_val(ei, e); dst = edge_val(ei, Ee + e); }
    else        { src = dst = e - Ee; }
    if ((unsigned)dst >= Nn || (unsigned)src >= Nn) return;
    int pos = atomicAdd(&g_wpos[dst], 1);
    if ((unsigned)pos < Etot) g_csr_src[pos] = src;
}

// ---------------- bf16x3 helpers ----------------
__device__ __forceinline__ unsigned pack_bf16(float f_even, float f_odd) {
    unsigned r;
    asm("cvt.rn.bf16x2.f32 %0, %1, %2;" : "=r"(r) : "f"(f_odd), "f"(f_even));
    return r;
}
__device__ __forceinline__ void split2(float f0, float f1, unsigned& hi, unsigned& lo) {
    hi = pack_bf16(f0, f1);
    float r0 = f0 - __uint_as_float(hi << 16);
    float r1 = f1 - __uint_as_float(hi & 0xFFFF0000u);
    lo = pack_bf16(r0, r1);
}
__device__ __forceinline__ void mma16(float c[4], const unsigned a[4], const unsigned b[2]) {
    asm("mma.sync.aligned.m16n8k16.row.col.f32.bf16.bf16.f32 "
        "{%0,%1,%2,%3},{%4,%5,%6,%7},{%8,%9},{%0,%1,%2,%3};"
        : "+f"(c[0]), "+f"(c[1]), "+f"(c[2]), "+f"(c[3])
        : "r"(a[0]), "r"(a[1]), "r"(a[2]), "r"(a[3]), "r"(b[0]), "r"(b[1]));
}

// ---------------- BN=64 GEMM, double-buffered smem (W3 + layers) ----------------
__global__ __launch_bounds__(256) void k_bf16gemm(
    const float* __restrict__ A,
    const float* __restrict__ B0, const float* __restrict__ bias0, float* __restrict__ C0,
    const float* __restrict__ B1, const float* __restrict__ bias1, float* __restrict__ C1,
    int M, int N, int K, int doRelu)
{
    const float* B    = (blockIdx.z == 0) ? B0 : B1;
    const float* bias = (blockIdx.z == 0) ? bias0 : bias1;
    float*       C    = (blockIdx.z == 0) ? C0 : C1;

    __shared__ unsigned As_hi[2][128][9], As_lo[2][128][9];
    __shared__ unsigned Bs_hi[2][64][9],  Bs_lo[2][64][9];

    int tid = threadIdx.x;
    int lane = tid & 31, warp = tid >> 5;
    int warpM = warp & 3, warpN = warp >> 2;
    int rowBase = blockIdx.y * 128;
    int colBase = blockIdx.x * 64;
    int lm = lane >> 2, lk = lane & 3;

    float acc[2][4][4];
#pragma unroll
    for (int mt = 0; mt < 2; mt++)
#pragma unroll
        for (int nt = 0; nt < 4; nt++)
#pragma unroll
            for (int i = 0; i < 4; i++) acc[mt][nt][i] = 0.f;

    int aRow = tid >> 2;
    int aCol = (tid & 3) * 4;
    int bKp  = tid >> 5;
    int bCol = (tid & 31) * 2;
    int gr0 = rowBase + aRow, gr1 = rowBase + 64 + aRow;

    int kIters = K >> 4;
    float4 aR0, aR1; float2 bR0, bR1;

    aR0 = (gr0 < M) ? *(const float4*)(A + (size_t)gr0 * K + aCol) : make_float4(0, 0, 0, 0);
    aR1 = (gr1 < M) ? *(const float4*)(A + (size_t)gr1 * K + aCol) : make_float4(0, 0, 0, 0);
    bR0 = *(const float2*)(B + (size_t)(bKp * 2)     * N + colBase + bCol);
    bR1 = *(const float2*)(B + (size_t)(bKp * 2 + 1) * N + colBase + bCol);
    {
        unsigned h, l;
        split2(aR0.x, aR0.y, h, l); As_hi[0][aRow][aCol / 2] = h;     As_lo[0][aRow][aCol / 2] = l;
        split2(aR0.z, aR0.w, h, l); As_hi[0][aRow][aCol / 2 + 1] = h; As_lo[0][aRow][aCol / 2 + 1] = l;
        split2(aR1.x, aR1.y, h, l); As_hi[0][64 + aRow][aCol / 2] = h;     As_lo[0][64 + aRow][aCol / 2] = l;
        split2(aR1.z, aR1.w, h, l); As_hi[0][64 + aRow][aCol / 2 + 1] = h; As_lo[0][64 + aRow][aCol / 2 + 1] = l;
        split2(bR0.x, bR1.x, h, l); Bs_hi[0][bCol][bKp] = h;     Bs_lo[0][bCol][bKp] = l;
        split2(bR0.y, bR1.y, h, l); Bs_hi[0][bCol + 1][bKp] = h; Bs_lo[0][bCol + 1][bKp] = l;
    }
    __syncthreads();

    for (int it = 0; it < kIters; it++) {
        int cb = it & 1, nb = cb ^ 1;
        if (it + 1 < kIters) {
            int k0 = (it + 1) * 16;
            aR0 = (gr0 < M) ? *(const float4*)(A + (size_t)gr0 * K + k0 + aCol) : make_float4(0, 0, 0, 0);
            aR1 = (gr1 < M) ? *(const float4*)(A + (size_t)gr1 * K + k0 + aCol) : make_float4(0, 0, 0, 0);
            bR0 = *(const float2*)(B + (size_t)(k0 + bKp * 2)     * N + colBase + bCol);
            bR1 = *(const float2*)(B + (size_t)(k0 + bKp * 2 + 1) * N + colBase + bCol);
        }

        unsigned ah[2][4], al[2][4], bh[4][2], bl[4][2];
#pragma unroll
        for (int mt = 0; mt < 2; mt++) {
            int rm = warpM * 32 + mt * 16 + lm;
            ah[mt][0] = As_hi[cb][rm][lk];     al[mt][0] = As_lo[cb][rm][lk];
            ah[mt][1] = As_hi[cb][rm + 8][lk]; al[mt][1] = As_lo[cb][rm + 8][lk];
            ah[mt][2] = As_hi[cb][rm][lk + 4];     al[mt][2] = As_lo[cb][rm][lk + 4];
            ah[mt][3] = As_hi[cb][rm + 8][lk + 4]; al[mt][3] = As_lo[cb][rm + 8][lk + 4];
        }
#pragma unroll
        for (int nt = 0; nt < 4; nt++) {
            int cn = warpN * 32 + nt * 8 + lm;
            bh[nt][0] = Bs_hi[cb][cn][lk];     bl[nt][0] = Bs_lo[cb][cn][lk];
            bh[nt][1] = Bs_hi[cb][cn][lk + 4]; bl[nt][1] = Bs_lo[cb][cn][lk + 4];
        }
#pragma unroll
        for (int mt = 0; mt < 2; mt++)
#pragma unroll
            for (int nt = 0; nt < 4; nt++) {
                mma16(acc[mt][nt], ah[mt], bl[nt]);
                mma16(acc[mt][nt], al[mt], bh[nt]);
                mma16(acc[mt][nt], ah[mt], bh[nt]);
            }

        if (it + 1 < kIters) {
            unsigned h, l;
            split2(aR0.x, aR0.y, h, l); As_hi[nb][aRow][aCol / 2] = h;     As_lo[nb][aRow][aCol / 2] = l;
            split2(aR0.z, aR0.w, h, l); As_hi[nb][aRow][aCol / 2 + 1] = h; As_lo[nb][aRow][aCol / 2 + 1] = l;
            split2(aR1.x, aR1.y, h, l); As_hi[nb][64 + aRow][aCol / 2] = h;     As_lo[nb][64 + aRow][aCol / 2] = l;
            split2(aR1.z, aR1.w, h, l); As_hi[nb][64 + aRow][aCol / 2 + 1] = h; As_lo[nb][64 + aRow][aCol / 2 + 1] = l;
            split2(bR0.x, bR1.x, h, l); Bs_hi[nb][bCol][bKp] = h;     Bs_lo[nb][bCol][bKp] = l;
            split2(bR0.y, bR1.y, h, l); Bs_hi[nb][bCol + 1][bKp] = h; Bs_lo[nb][bCol + 1][bKp] = l;
            __syncthreads();
        }
    }

#pragma unroll
    for (int mt = 0; mt < 2; mt++) {
        int r0 = rowBase + warpM * 32 + mt * 16 + lm;
#pragma unroll
        for (int nt = 0; nt < 4; nt++) {
            int col = colBase + warpN * 32 + nt * 8 + lk * 2;
            float bb0 = bias ? bias[col] : 0.f;
            float bb1 = bias ? bias[col + 1] : 0.f;
            float v0 = acc[mt][nt][0] + bb0, v1 = acc[mt][nt][1] + bb1;
            float v2 = acc[mt][nt][2] + bb0, v3 = acc[mt][nt][3] + bb1;
            if (doRelu) {
                v0 = fmaxf(v0, 0.f); v1 = fmaxf(v1, 0.f);
                v2 = fmaxf(v2, 0.f); v3 = fmaxf(v3, 0.f);
            }
            if (r0 < M)     *(float2*)(C + (size_t)r0 * N + col)       = make_float2(v0, v1);
            if (r0 + 8 < M) *(float2*)(C + (size_t)(r0 + 8) * N + col) = make_float2(v2, v3);
        }
    }
}

// ---------------- BN=128 GEMM, warp tile 64x32, double-buffered (W1/W2) ----------------
__global__ __launch_bounds__(256) void k_gemm128(
    const float* __restrict__ A, const float* __restrict__ B,
    const float* __restrict__ bias, float* __restrict__ C,
    int M, int N, int K, int doRelu)
{
    __shared__ unsigned As_hi[2][128][9], As_lo[2][128][9];
    __shared__ unsigned Bs_hi[2][128][9], Bs_lo[2][128][9];

    int tid = threadIdx.x;
    int lane = tid & 31, warp = tid >> 5;
    int warpM = warp >> 2;
    int warpN = warp & 3;
    int rowBase = blockIdx.y * 128;
    int colBase = blockIdx.x * 128;
    int lm = lane >> 2, lk = lane & 3;

    float acc[4][4][4];
#pragma unroll
    for (int mt = 0; mt < 4; mt++)
#pragma unroll
        for (int nt = 0; nt < 4; nt++)
#pragma unroll
            for (int i = 0; i < 4; i++) acc[mt][nt][i] = 0.f;

    int aRow = tid >> 2;
    int aCol = (tid & 3) * 4;
    int bKp  = tid >> 6;
    int bCol = (tid & 63) * 2;
    int gr0 = rowBase + aRow, gr1 = rowBase + 64 + aRow;

    int kIters = K >> 4;
    float4 aR0, aR1;
    float2 bA0, bA1, bB0, bB1;

    aR0 = (gr0 < M) ? *(const float4*)(A + (size_t)gr0 * K + aCol) : make_float4(0, 0, 0, 0);
    aR1 = (gr1 < M) ? *(const float4*)(A + (size_t)gr1 * K + aCol) : make_float4(0, 0, 0, 0);
    {
        const float* bp = B + colBase + bCol;
        bA0 = *(const float2*)(bp + (size_t)(bKp * 2) * N);
        bA1 = *(const float2*)(bp + (size_t)(bKp * 2 + 1) * N);
        bB0 = *(const float2*)(bp + (size_t)((bKp + 4) * 2) * N);
        bB1 = *(const float2*)(bp + (size_t)((bKp + 4) * 2 + 1) * N);
    }
    {
        unsigned h, l;
        split2(aR0.x, aR0.y, h, l); As_hi[0][aRow][aCol / 2] = h;     As_lo[0][aRow][aCol / 2] = l;
        split2(aR0.z, aR0.w, h, l); As_hi[0][aRow][aCol / 2 + 1] = h; As_lo[0][aRow][aCol / 2 + 1] = l;
        split2(aR1.x, aR1.y, h, l); As_hi[0][64 + aRow][aCol / 2] = h;     As_lo[0][64 + aRow][aCol / 2] = l;
        split2(aR1.z, aR1.w, h, l); As_hi[0][64 + aRow][aCol / 2 + 1] = h; As_lo[0][64 + aRow][aCol / 2 + 1] = l;
        split2(bA0.x, bA1.x, h, l); Bs_hi[0][bCol][bKp] = h;     Bs_lo[0][bCol][bKp] = l;
        split2(bA0.y, bA1.y, h, l); Bs_hi[0][bCol + 1][bKp] = h; Bs_lo[0][bCol + 1][bKp] = l;
        split2(bB0.x, bB1.x, h, l); Bs_hi[0][bCol][bKp + 4] = h;     Bs_lo[0][bCol][bKp + 4] = l;
        split2(bB0.y, bB1.y, h, l); Bs_hi[0][bCol + 1][bKp + 4] = h; Bs_lo[0][bCol + 1][bKp + 4] = l;
    }
    __syncthreads();

    for (int it = 0; it < kIters; it++) {
        int cb = it & 1, nb = cb ^ 1;
        if (it + 1 < kIters) {
            int k0 = (it + 1) * 16;
            aR0 = (gr0 < M) ? *(const float4*)(A + (size_t)gr0 * K + k0 + aCol) : make_float4(0, 0, 0, 0);
            aR1 = (gr1 < M) ? *(const float4*)(A + (size_t)gr1 * K + k0 + aCol) : make_float4(0, 0, 0, 0);
            const float* bp = B + colBase + bCol;
            bA0 = *(const float2*)(bp + (size_t)(k0 + bKp * 2) * N);
            bA1 = *(const float2*)(bp + (size_t)(k0 + bKp * 2 + 1) * N);
            bB0 = *(const float2*)(bp + (size_t)(k0 + (bKp + 4) * 2) * N);
            bB1 = *(const float2*)(bp + (size_t)(k0 + (bKp + 4) * 2 + 1) * N);
        }

        unsigned ah[4][4], al[4][4], bh[4][2], bl[4][2];
#pragma unroll
        for (int mt = 0; mt < 4; mt++) {
            int rm = warpM * 64 + mt * 16 + lm;
            ah[mt][0] = As_hi[cb][rm][lk];     al[mt][0] = As_lo[cb][rm][lk];
            ah[mt][1] = As_hi[cb][rm + 8][lk]; al[mt][1] = As_lo[cb][rm + 8][lk];
            ah[mt][2] = As_hi[cb][rm][lk + 4];     al[mt][2] = As_lo[cb][rm][lk + 4];
            ah[mt][3] = As_hi[cb][rm + 8][lk + 4]; al[mt][3] = As_lo[cb][rm + 8][lk + 4];
        }
#pragma unroll
        for (int nt = 0; nt < 4; nt++) {
            int cn = warpN * 32 + nt * 8 + lm;
            bh[nt][0] = Bs_hi[cb][cn][lk];     bl[nt][0] = Bs_lo[cb][cn][lk];
            bh[nt][1] = Bs_hi[cb][cn][lk + 4]; bl[nt][1] = Bs_lo[cb][cn][lk + 4];
        }
#pragma unroll
        for (int mt = 0; mt < 4; mt++)
#pragma unroll
            for (int nt = 0; nt < 4; nt++) {
                mma16(acc[mt][nt], ah[mt], bl[nt]);
                mma16(acc[mt][nt], al[mt], bh[nt]);
                mma16(acc[mt][nt], ah[mt], bh[nt]);
            }

        if (it + 1 < kIters) {
            unsigned h, l;
            split2(aR0.x, aR0.y, h, l); As_hi[nb][aRow][aCol / 2] = h;     As_lo[nb][aRow][aCol / 2] = l;
            split2(aR0.z, aR0.w, h, l); As_hi[nb][aRow][aCol / 2 + 1] = h; As_lo[nb][aRow][aCol / 2 + 1] = l;
            split2(aR1.x, aR1.y, h, l); As_hi[nb][64 + aRow][aCol / 2] = h;     As_lo[nb][64 + aRow][aCol / 2] = l;
            split2(aR1.z, aR1.w, h, l); As_hi[nb][64 + aRow][aCol / 2 + 1] = h; As_lo[nb][64 + aRow][aCol / 2 + 1] = l;
            split2(bA0.x, bA1.x, h, l); Bs_hi[nb][bCol][bKp] = h;     Bs_lo[nb][bCol][bKp] = l;
            split2(bA0.y, bA1.y, h, l); Bs_hi[nb][bCol + 1][bKp] = h; Bs_lo[nb][bCol + 1][bKp] = l;
            split2(bB0.x, bB1.x, h, l); Bs_hi[nb][bCol][bKp + 4] = h;     Bs_lo[nb][bCol][bKp + 4] = l;
            split2(bB0.y, bB1.y, h, l); Bs_hi[nb][bCol + 1][bKp + 4] = h; Bs_lo[nb][bCol + 1][bKp + 4] = l;
            __syncthreads();
        }
    }

#pragma unroll
    for (int mt = 0; mt < 4; mt++) {
        int r0 = rowBase + warpM * 64 + mt * 16 + lm;
#pragma unroll
        for (int nt = 0; nt < 4; nt++) {
            int col = colBase + warpN * 32 + nt * 8 + lk * 2;
            float bb0 = bias ? bias[col] : 0.f;
            float bb1 = bias ? bias[col + 1] : 0.f;
            float v0 = acc[mt][nt][0] + bb0, v1 = acc[mt][nt][1] + bb1;
            float v2 = acc[mt][nt][2] + bb0, v3 = acc[mt][nt][3] + bb1;
            if (doRelu) {
                v0 = fmaxf(v0, 0.f); v1 = fmaxf(v1, 0.f);
                v2 = fmaxf(v2, 0.f); v3 = fmaxf(v3, 0.f);
            }
            if (r0 < M)     *(float2*)(C + (size_t)r0 * N + col)       = make_float2(v0, v1);
            if (r0 + 8 < M) *(float2*)(C + (size_t)(r0 + 8) * N + col) = make_float2(v2, v3);
        }
    }
}

// ---------------- per-dst GATv2 aggregation (proven R8 version) ----------------
__global__ __launch_bounds__(256) void k_gat_dst(
    const float* __restrict__ xl, const float* __restrict__ xr,
    const float* __restrict__ att, const float* __restrict__ cbias,
    float* __restrict__ hout)
{
    __shared__ float sh_xr[HC];
    __shared__ float sh_out[Hh][Cc];

    int dst = blockIdx.x;
    int tid = threadIdx.x;
    for (int i = tid; i < HC; i += 256) sh_xr[i] = xr[(size_t)dst * HC + i];
    __syncthreads();

    int wid = tid >> 5, lane = tid & 31;
    if (wid < Hh) {
        int h = wid;
        float att0 = att[h * Cc + lane];
        float att1 = att[h * Cc + 32 + lane];
        float xr0 = sh_xr[h * Cc + lane];
        float xr1 = sh_xr[h * Cc + 32 + lane];

        float s = 0.f, a0 = 0.f, a1 = 0.f;
        int beg = g_rowptr[dst], end = g_rowptr[dst + 1];
        const int* csr = g_csr_src;
#pragma unroll 4
        for (int i = beg; i < end; i++) {
            int src = csr[i];
            const float* row = xl + (size_t)src * HC + h * Cc;
            float x0 = row[lane];
            float x1 = row[lane + 32];
            float v0 = x0 + xr0; v0 = (v0 > 0.f) ? v0 : 0.2f * v0;
            float v1 = x1 + xr1; v1 = (v1 > 0.f) ? v1 : 0.2f * v1;
            float p = v0 * att0 + v1 * att1;
#pragma unroll
            for (int o = 16; o; o >>= 1) p += __shfl_xor_sync(0xFFFFFFFFu, p, o);
            float w = __expf(p);
            s  += w;
            a0 += w * x0;
            a1 += w * x1;
        }
        float inv = 1.f / (s + 1e-16f);
        sh_out[h][lane]      = a0 * inv;
        sh_out[h][lane + 32] = a1 * inv;
    }
    __syncthreads();

    if (tid < Cc) {
        float v = 0.f;
#pragma unroll
        for (int h = 0; h < Hh; h++) v += sh_out[h][tid];
        v = v * (1.f / 7.f) + cbias[tid];
        hout[(size_t)dst * Cc + tid] = fmaxf(v, 0.f);
    }
}

// ---------------- fused output MLP + log_softmax ----------------
__global__ __launch_bounds__(128) void k_outmlp(
    const float* __restrict__ h,
    const float* __restrict__ V1, const float* __restrict__ c1,
    const float* __restrict__ V2, const float* __restrict__ c2,
    const float* __restrict__ V3, const float* __restrict__ c3,
    float* __restrict__ out)
{
    __shared__ float sV1[64 * 32], sV2[32 * 16], sV3[16 * 9];
    __shared__ float sc1[32], sc2[16], sc3[9];
    int tid = threadIdx.x;
    for (int i = tid; i < 64 * 32; i += 128) sV1[i] = V1[i];
    for (int i = tid; i < 32 * 16; i += 128) sV2[i] = V2[i];
    for (int i = tid; i < 16 * 9; i += 128)  sV3[i] = V3[i];
    if (tid < 32) sc1[tid] = c1[tid];
    if (tid < 16) sc2[tid] = c2[tid];
    if (tid < 9)  sc3[tid] = c3[tid];
    __syncthreads();

    int row = blockIdx.x * 128 + tid;
    if (row >= Nn) return;

    float x[64];
#pragma unroll
    for (int k = 0; k < 64; k++) x[k] = fmaxf(h[(size_t)row * 64 + k], 0.f);

    float t1[32];
#pragma unroll
    for (int j = 0; j < 32; j++) {
        float v = sc1[j];
#pragma unroll
        for (int k = 0; k < 64; k++) v += x[k] * sV1[k * 32 + j];
        t1[j] = fmaxf(v, 0.f);
    }
    float t2[16];
#pragma unroll
    for (int j = 0; j < 16; j++) {
        float v = sc2[j];
#pragma unroll
        for (int k = 0; k < 32; k++) v += t1[k] * sV2[k * 16 + j];
        t2[j] = fmaxf(v, 0.f);
    }
    float t3[9];
    float mx = -INFINITY;
#pragma unroll
    for (int j = 0; j < 9; j++) {
        float v = sc3[j];
#pragma unroll
        for (int k = 0; k < 16; k++) v += t2[k] * sV3[k * 9 + j];
        t3[j] = v;
        mx = fmaxf(mx, v);
    }
    float se = 0.f;
#pragma unroll
    for (int j = 0; j < 9; j++) se += expf(t3[j] - mx);
    float lse = logf(se) + mx;
#pragma unroll
    for (int j = 0; j < 9; j++) out[(size_t)row * 9 + j] = t3[j] - lse;
}

// ---------------- host ----------------
static void launch_gemm64(const float* A, const float* B, const float* bias,
                          float* C, int M, int N, int K, int relu)
{
    dim3 grid(N / 64, (M + 127) / 128, 1);
    k_bf16gemm<<<grid, 256>>>(A, B, bias, C, B, bias, C, M, N, K, relu);
}
static void launch_gemm128(const float* A, const float* B, const float* bias,
                           float* C, int M, int N, int K, int relu)
{
    dim3 grid(N / 128, (M + 127) / 128, 1);
    k_gemm128<<<grid, 256>>>(A, B, bias, C, M, N, K, relu);
}

extern "C" void kernel_launch(void* const* d_in, const int* in_sizes, int n_in,
                              void* d_out, int out_size)
{
    const float* x  = (const float*)d_in[0];
    const void*  ei = d_in[1];
    const float* W1 = (const float*)d_in[2];  const float* b1 = (const float*)d_in[3];
    const float* W2 = (const float*)d_in[4];  const float* b2 = (const float*)d_in[5];
    const float* W3 = (const float*)d_in[6];  const float* b3 = (const float*)d_in[7];
    const float* Wl = (const float*)d_in[8];  const float* bl = (const float*)d_in[9];
    const float* Wr = (const float*)d_in[10];
    const float* att   = (const float*)d_in[11];
    const float* cbias = (const float*)d_in[12];
    const float* V1 = (const float*)d_in[13]; const float* c1 = (const float*)d_in[14];
    const float* V2 = (const float*)d_in[15]; const float* c2 = (const float*)d_in[16];
    const float* V3 = (const float*)d_in[17]; const float* c3 = (const float*)d_in[18];
    float* out = (float*)d_out;

    float *p_h0, *p_h1, *p_hA, *p_hB, *p_xl, *p_xr;
    cudaGetSymbolAddress((void**)&p_h0, g_h0);
    cudaGetSymbolAddress((void**)&p_h1, g_h1);
    cudaGetSymbolAddress((void**)&p_hA, g_hA);
    cudaGetSymbolAddress((void**)&p_hB, g_hB);
    cudaGetSymbolAddress((void**)&p_xl, g_xl);
    cudaGetSymbolAddress((void**)&p_xr, g_xr);

    // lazily-created side stream + events (one-time; not allocations in the graph)
    static cudaStream_t s_side = 0;
    static cudaEvent_t ev_fork = 0, ev_join = 0;
    if (!s_side) {
        cudaStreamCreateWithFlags(&s_side, cudaStreamNonBlocking);
        cudaEventCreateWithFlags(&ev_fork, cudaEventDisableTiming);
        cudaEventCreateWithFlags(&ev_join, cudaEventDisableTiming);
    }

    // fork: CSR build runs on side stream, concurrent with the input MLP
    cudaEventRecord(ev_fork, 0);
    cudaStreamWaitEvent(s_side, ev_fork, 0);

    k_detect<<<1, 256, 0, s_side>>>((const int*)ei);
    k_clear_deg<<<(Nn + 255) / 256, 256, 0, s_side>>>();
    k_count<<<(Etot + 255) / 256, 256, 0, s_side>>>(ei);
    k_scan<<<1, 1024, 0, s_side>>>();
    k_scatter<<<(Etot + 255) / 256, 256, 0, s_side>>>(ei);
    cudaEventRecord(ev_join, s_side);

    // main stream: input MLP (does not depend on CSR)
    launch_gemm128(x, W1, b1, p_h0, Nn, 512, 1024, 1);
    launch_gemm128(p_h0, W2, b2, p_h1, Nn, 256, 512, 1);
    launch_gemm64(p_h1, W3, b3, p_hA, Nn, 64, 256, 1);

    float* cur = p_hA;
    float* nxt = p_hB;
    for (int l = 0; l < 5; l++) {
        const float* Wl_l = Wl + (size_t)l * 64 * HC;
        const float* bl_l = bl + (size_t)l * HC;
        const float* Wr_l = Wr + (size_t)l * 64 * HC;
        const float* att_l = att + (size_t)l * Hh * Cc;
        const float* cb_l  = cbias + (size_t)l * Cc;
        dim3 grid(HC / 64, (Nn + 127) / 128, 2);
        k_bf16gemm<<<grid, 256>>>(cur, Wl_l, bl_l, p_xl, Wr_l, nullptr, p_xr,
                                  Nn, HC, 64, 0);
        if (l == 0) cudaStreamWaitEvent(0, ev_join, 0);   // join before first CSR consumer
        k_gat_dst<<<Nn, 256>>>(p_xl, p_xr, att_l, cb_l, nxt);
        float* t = cur; cur = nxt; nxt = t;
    }

    k_outmlp<<<(Nn + 127) / 128, 128>>>(cur, V1, c1, V2, c2, V3, c3, out);
}

// round 16
// speedup vs baseline: 1.6360x; 1.5022x over previous
#include <cuda_runtime.h>
#include <math.h>

#define Nn 10000
#define Ee 160000
#define Etot (Ee + Nn)
#define Hh 7
#define Cc 64
#define HC 448

// ---------------- scratch ----------------
__device__ float g_h0[Nn * 512];
__device__ float g_h1[Nn * 256];
__device__ float g_hA[Nn * 64];
__device__ float g_hB[Nn * 64];
__device__ float g_xl[Nn * HC];
__device__ float g_xr[Nn * HC];
__device__ int   g_deg[Nn];
__device__ int   g_rowptr[Nn + 1];
__device__ int   g_wpos[Nn];
__device__ int   g_csr_src[Etot];
__device__ int   g_is64;

// ---------------- edge dtype detection (parallel) ----------------
__global__ void k_detect(const int* __restrict__ ei32) {
    int nz = (ei32[2 * threadIdx.x + 1] != 0) ? 1 : 0;
    int tot = __syncthreads_count(nz);
    if (threadIdx.x == 0) g_is64 = (tot == 0) ? 1 : 0;
}
__device__ __forceinline__ int edge_val(const void* ei, int idx) {
    if (g_is64) return (int)((const long long*)ei)[idx];
    return ((const int*)ei)[idx];
}

// ---------------- CSR build ----------------
__global__ void k_clear_deg() {
    int i = blockIdx.x * blockDim.x + threadIdx.x;
    if (i < Nn) g_deg[i] = 0;
}
__global__ void k_count(const void* __restrict__ ei) {
    int e = blockIdx.x * blockDim.x + threadIdx.x;
    if (e >= Etot) return;
    int dst = (e < Ee) ? edge_val(ei, Ee + e) : (e - Ee);
    if ((unsigned)dst < Nn) atomicAdd(&g_deg[dst], 1);
}

__global__ void k_scan() {
    int t = threadIdx.x;
    int base = t * 10;
    int v[10]; int s = 0;
#pragma unroll
    for (int i = 0; i < 10; i++) {
        int idx = base + i;
        v[i] = (idx < Nn) ? g_deg[idx] : 0;
        s += v[i];
    }
    int lane = t & 31, wid = t >> 5;
    int ss = s;
#pragma unroll
    for (int o = 1; o < 32; o <<= 1) {
        int u = __shfl_up_sync(0xFFFFFFFFu, ss, o);
        if (lane >= o) ss += u;
    }
    __shared__ int wsum[32];
    if (lane == 31) wsum[wid] = ss;
    __syncthreads();
    if (wid == 0) {
        int w = wsum[lane];
#pragma unroll
        for (int o = 1; o < 32; o <<= 1) {
            int u = __shfl_up_sync(0xFFFFFFFFu, w, o);
            if (lane >= o) w += u;
        }
        wsum[lane] = w;
    }
    __syncthreads();
    int excl = ss - s + (wid ? wsum[wid - 1] : 0);
    int run = excl;
#pragma unroll
    for (int i = 0; i < 10; i++) {
        int idx = base + i;
        if (idx < Nn) {
            g_wpos[idx] = run;
            run += v[i];
            g_rowptr[idx + 1] = run;
        }
    }
    if (t == 0) g_rowptr[0] = 0;
}

__global__ void k_scatter(const void* __restrict__ ei) {
    int e = blockIdx.x * blockDim.x + threadIdx.x;
    if (e >= Etot) return;
    int src, dst;
    if (e < Ee) { src = edge_val(ei, e); dst = edge_val(ei, Ee + e); }
    else        { src = dst = e - Ee; }
    if ((unsigned)dst >= Nn || (unsigned)src >= Nn) return;
    int pos = atomicAdd(&g_wpos[dst], 1);
    if ((unsigned)pos < Etot) g_csr_src[pos] = src;
}

// ---------------- bf16x3 helpers ----------------
__device__ __forceinline__ unsigned pack_bf16(float f_even, float f_odd) {
    unsigned r;
    asm("cvt.rn.bf16x2.f32 %0, %1, %2;" : "=r"(r) : "f"(f_odd), "f"(f_even));
    return r;
}
__device__ __forceinline__ void split2(float f0, float f1, unsigned& hi, unsigned& lo) {
    hi = pack_bf16(f0, f1);
    float r0 = f0 - __uint_as_float(hi << 16);
    float r1 = f1 - __uint_as_float(hi & 0xFFFF0000u);
    lo = pack_bf16(r0, r1);
}
__device__ __forceinline__ void mma16(float c[4], const unsigned a[4], const unsigned b[2]) {
    asm("mma.sync.aligned.m16n8k16.row.col.f32.bf16.bf16.f32 "
        "{%0,%1,%2,%3},{%4,%5,%6,%7},{%8,%9},{%0,%1,%2,%3};"
        : "+f"(c[0]), "+f"(c[1]), "+f"(c[2]), "+f"(c[3])
        : "r"(a[0]), "r"(a[1]), "r"(a[2]), "r"(a[3]), "r"(b[0]), "r"(b[1]));
}

// ---------------- BN=64 GEMM, double-buffered smem (W3 + layers) ----------------
__global__ __launch_bounds__(256) void k_bf16gemm(
    const float* __restrict__ A,
    const float* __restrict__ B0, const float* __restrict__ bias0, float* __restrict__ C0,
    const float* __restrict__ B1, const float* __restrict__ bias1, float* __restrict__ C1,
    int M, int N, int K, int doRelu)
{
    const float* B    = (blockIdx.z == 0) ? B0 : B1;
    const float* bias = (blockIdx.z == 0) ? bias0 : bias1;
    float*       C    = (blockIdx.z == 0) ? C0 : C1;

    __shared__ unsigned As_hi[2][128][9], As_lo[2][128][9];
    __shared__ unsigned Bs_hi[2][64][9],  Bs_lo[2][64][9];

    int tid = threadIdx.x;
    int lane = tid & 31, warp = tid >> 5;
    int warpM = warp & 3, warpN = warp >> 2;
    int rowBase = blockIdx.y * 128;
    int colBase = blockIdx.x * 64;
    int lm = lane >> 2, lk = lane & 3;

    float acc[2][4][4];
#pragma unroll
    for (int mt = 0; mt < 2; mt++)
#pragma unroll
        for (int nt = 0; nt < 4; nt++)
#pragma unroll
            for (int i = 0; i < 4; i++) acc[mt][nt][i] = 0.f;

    int aRow = tid >> 2;
    int aCol = (tid & 3) * 4;
    int bKp  = tid >> 5;
    int bCol = (tid & 31) * 2;
    int gr0 = rowBase + aRow, gr1 = rowBase + 64 + aRow;

    int kIters = K >> 4;
    float4 aR0, aR1; float2 bR0, bR1;

    aR0 = (gr0 < M) ? *(const float4*)(A + (size_t)gr0 * K + aCol) : make_float4(0, 0, 0, 0);
    aR1 = (gr1 < M) ? *(const float4*)(A + (size_t)gr1 * K + aCol) : make_float4(0, 0, 0, 0);
    bR0 = *(const float2*)(B + (size_t)(bKp * 2)     * N + colBase + bCol);
    bR1 = *(const float2*)(B + (size_t)(bKp * 2 + 1) * N + colBase + bCol);
    {
        unsigned h, l;
        split2(aR0.x, aR0.y, h, l); As_hi[0][aRow][aCol / 2] = h;     As_lo[0][aRow][aCol / 2] = l;
        split2(aR0.z, aR0.w, h, l); As_hi[0][aRow][aCol / 2 + 1] = h; As_lo[0][aRow][aCol / 2 + 1] = l;
        split2(aR1.x, aR1.y, h, l); As_hi[0][64 + aRow][aCol / 2] = h;     As_lo[0][64 + aRow][aCol / 2] = l;
        split2(aR1.z, aR1.w, h, l); As_hi[0][64 + aRow][aCol / 2 + 1] = h; As_lo[0][64 + aRow][aCol / 2 + 1] = l;
        split2(bR0.x, bR1.x, h, l); Bs_hi[0][bCol][bKp] = h;     Bs_lo[0][bCol][bKp] = l;
        split2(bR0.y, bR1.y, h, l); Bs_hi[0][bCol + 1][bKp] = h; Bs_lo[0][bCol + 1][bKp] = l;
    }
    __syncthreads();

    for (int it = 0; it < kIters; it++) {
        int cb = it & 1, nb = cb ^ 1;
        if (it + 1 < kIters) {
            int k0 = (it + 1) * 16;
            aR0 = (gr0 < M) ? *(const float4*)(A + (size_t)gr0 * K + k0 + aCol) : make_float4(0, 0, 0, 0);
            aR1 = (gr1 < M) ? *(const float4*)(A + (size_t)gr1 * K + k0 + aCol) : make_float4(0, 0, 0, 0);
            bR0 = *(const float2*)(B + (size_t)(k0 + bKp * 2)     * N + colBase + bCol);
            bR1 = *(const float2*)(B + (size_t)(k0 + bKp * 2 + 1) * N + colBase + bCol);
        }

        unsigned ah[2][4], al[2][4], bh[4][2], bl[4][2];
#pragma unroll
        for (int mt = 0; mt < 2; mt++) {
            int rm = warpM * 32 + mt * 16 + lm;
            ah[mt][0] = As_hi[cb][rm][lk];     al[mt][0] = As_lo[cb][rm][lk];
            ah[mt][1] = As_hi[cb][rm + 8][lk]; al[mt][1] = As_lo[cb][rm + 8][lk];
            ah[mt][2] = As_hi[cb][rm][lk + 4];     al[mt][2] = As_lo[cb][rm][lk + 4];
            ah[mt][3] = As_hi[cb][rm + 8][lk + 4]; al[mt][3] = As_lo[cb][rm + 8][lk + 4];
        }
#pragma unroll
        for (int nt = 0; nt < 4; nt++) {
            int cn = warpN * 32 + nt * 8 + lm;
            bh[nt][0] = Bs_hi[cb][cn][lk];     bl[nt][0] = Bs_lo[cb][cn][lk];
            bh[nt][1] = Bs_hi[cb][cn][lk + 4]; bl[nt][1] = Bs_lo[cb][cn][lk + 4];
        }
#pragma unroll
        for (int mt = 0; mt < 2; mt++)
#pragma unroll
            for (int nt = 0; nt < 4; nt++) {
                mma16(acc[mt][nt], ah[mt], bl[nt]);
                mma16(acc[mt][nt], al[mt], bh[nt]);
                mma16(acc[mt][nt], ah[mt], bh[nt]);
            }

        if (it + 1 < kIters) {
            unsigned h, l;
            split2(aR0.x, aR0.y, h, l); As_hi[nb][aRow][aCol / 2] = h;     As_lo[nb][aRow][aCol / 2] = l;
            split2(aR0.z, aR0.w, h, l); As_hi[nb][aRow][aCol / 2 + 1] = h; As_lo[nb][aRow][aCol / 2 + 1] = l;
            split2(aR1.x, aR1.y, h, l); As_hi[nb][64 + aRow][aCol / 2] = h;     As_lo[nb][64 + aRow][aCol / 2] = l;
            split2(aR1.z, aR1.w, h, l); As_hi[nb][64 + aRow][aCol / 2 + 1] = h; As_lo[nb][64 + aRow][aCol / 2 + 1] = l;
            split2(bR0.x, bR1.x, h, l); Bs_hi[nb][bCol][bKp] = h;     Bs_lo[nb][bCol][bKp] = l;
            split2(bR0.y, bR1.y, h, l); Bs_hi[nb][bCol + 1][bKp] = h; Bs_lo[nb][bCol + 1][bKp] = l;
            __syncthreads();
        }
    }

#pragma unroll
    for (int mt = 0; mt < 2; mt++) {
        int r0 = rowBase + warpM * 32 + mt * 16 + lm;
#pragma unroll
        for (int nt = 0; nt < 4; nt++) {
            int col = colBase + warpN * 32 + nt * 8 + lk * 2;
            float bb0 = bias ? bias[col] : 0.f;
            float bb1 = bias ? bias[col + 1] : 0.f;
            float v0 = acc[mt][nt][0] + bb0, v1 = acc[mt][nt][1] + bb1;
            float v2 = acc[mt][nt][2] + bb0, v3 = acc[mt][nt][3] + bb1;
            if (doRelu) {
                v0 = fmaxf(v0, 0.f); v1 = fmaxf(v1, 0.f);
                v2 = fmaxf(v2, 0.f); v3 = fmaxf(v3, 0.f);
            }
            if (r0 < M)     *(float2*)(C + (size_t)r0 * N + col)       = make_float2(v0, v1);
            if (r0 + 8 < M) *(float2*)(C + (size_t)(r0 + 8) * N + col) = make_float2(v2, v3);
        }
    }
}

// ---------------- BN=128 GEMM, warp tile 64x32, double-buffered (W1/W2) ----------------
__global__ __launch_bounds__(256) void k_gemm128(
    const float* __restrict__ A, const float* __restrict__ B,
    const float* __restrict__ bias, float* __restrict__ C,
    int M, int N, int K, int doRelu)
{
    __shared__ unsigned As_hi[2][128][9], As_lo[2][128][9];
    __shared__ unsigned Bs_hi[2][128][9], Bs_lo[2][128][9];

    int tid = threadIdx.x;
    int lane = tid & 31, warp = tid >> 5;
    int warpM = warp >> 2;
    int warpN = warp & 3;
    int rowBase = blockIdx.y * 128;
    int colBase = blockIdx.x * 128;
    int lm = lane >> 2, lk = lane & 3;

    float acc[4][4][4];
#pragma unroll
    for (int mt = 0; mt < 4; mt++)
#pragma unroll
        for (int nt = 0; nt < 4; nt++)
#pragma unroll
            for (int i = 0; i < 4; i++) acc[mt][nt][i] = 0.f;

    int aRow = tid >> 2;
    int aCol = (tid & 3) * 4;
    int bKp  = tid >> 6;
    int bCol = (tid & 63) * 2;
    int gr0 = rowBase + aRow, gr1 = rowBase + 64 + aRow;

    int kIters = K >> 4;
    float4 aR0, aR1;
    float2 bA0, bA1, bB0, bB1;

    aR0 = (gr0 < M) ? *(const float4*)(A + (size_t)gr0 * K + aCol) : make_float4(0, 0, 0, 0);
    aR1 = (gr1 < M) ? *(const float4*)(A + (size_t)gr1 * K + aCol) : make_float4(0, 0, 0, 0);
    {
        const float* bp = B + colBase + bCol;
        bA0 = *(const float2*)(bp + (size_t)(bKp * 2) * N);
        bA1 = *(const float2*)(bp + (size_t)(bKp * 2 + 1) * N);
        bB0 = *(const float2*)(bp + (size_t)((bKp + 4) * 2) * N);
        bB1 = *(const float2*)(bp + (size_t)((bKp + 4) * 2 + 1) * N);
    }
    {
        unsigned h, l;
        split2(aR0.x, aR0.y, h, l); As_hi[0][aRow][aCol / 2] = h;     As_lo[0][aRow][aCol / 2] = l;
        split2(aR0.z, aR0.w, h, l); As_hi[0][aRow][aCol / 2 + 1] = h; As_lo[0][aRow][aCol / 2 + 1] = l;
        split2(aR1.x, aR1.y, h, l); As_hi[0][64 + aRow][aCol / 2] = h;     As_lo[0][64 + aRow][aCol / 2] = l;
        split2(aR1.z, aR1.w, h, l); As_hi[0][64 + aRow][aCol / 2 + 1] = h; As_lo[0][64 + aRow][aCol / 2 + 1] = l;
        split2(bA0.x, bA1.x, h, l); Bs_hi[0][bCol][bKp] = h;     Bs_lo[0][bCol][bKp] = l;
        split2(bA0.y, bA1.y, h, l); Bs_hi[0][bCol + 1][bKp] = h; Bs_lo[0][bCol + 1][bKp] = l;
        split2(bB0.x, bB1.x, h, l); Bs_hi[0][bCol][bKp + 4] = h;     Bs_lo[0][bCol][bKp + 4] = l;
        split2(bB0.y, bB1.y, h, l); Bs_hi[0][bCol + 1][bKp + 4] = h; Bs_lo[0][bCol + 1][bKp + 4] = l;
    }
    __syncthreads();

    for (int it = 0; it < kIters; it++) {
        int cb = it & 1, nb = cb ^ 1;
        if (it + 1 < kIters) {
            int k0 = (it + 1) * 16;
            aR0 = (gr0 < M) ? *(const float4*)(A + (size_t)gr0 * K + k0 + aCol) : make_float4(0, 0, 0, 0);
            aR1 = (gr1 < M) ? *(const float4*)(A + (size_t)gr1 * K + k0 + aCol) : make_float4(0, 0, 0, 0);
            const float* bp = B + colBase + bCol;
            bA0 = *(const float2*)(bp + (size_t)(k0 + bKp * 2) * N);
            bA1 = *(const float2*)(bp + (size_t)(k0 + bKp * 2 + 1) * N);
            bB0 = *(const float2*)(bp + (size_t)(k0 + (bKp + 4) * 2) * N);
            bB1 = *(const float2*)(bp + (size_t)(k0 + (bKp + 4) * 2 + 1) * N);
        }

        unsigned ah[4][4], al[4][4], bh[4][2], bl[4][2];
#pragma unroll
        for (int mt = 0; mt < 4; mt++) {
            int rm = warpM * 64 + mt * 16 + lm;
            ah[mt][0] = As_hi[cb][rm][lk];     al[mt][0] = As_lo[cb][rm][lk];
            ah[mt][1] = As_hi[cb][rm + 8][lk]; al[mt][1] = As_lo[cb][rm + 8][lk];
            ah[mt][2] = As_hi[cb][rm][lk + 4];     al[mt][2] = As_lo[cb][rm][lk + 4];
            ah[mt][3] = As_hi[cb][rm + 8][lk + 4]; al[mt][3] = As_lo[cb][rm + 8][lk + 4];
        }
#pragma unroll
        for (int nt = 0; nt < 4; nt++) {
            int cn = warpN * 32 + nt * 8 + lm;
            bh[nt][0] = Bs_hi[cb][cn][lk];     bl[nt][0] = Bs_lo[cb][cn][lk];
            bh[nt][1] = Bs_hi[cb][cn][lk + 4]; bl[nt][1] = Bs_lo[cb][cn][lk + 4];
        }
#pragma unroll
        for (int mt = 0; mt < 4; mt++)
#pragma unroll
            for (int nt = 0; nt < 4; nt++) {
                mma16(acc[mt][nt], ah[mt], bl[nt]);
                mma16(acc[mt][nt], al[mt], bh[nt]);
                mma16(acc[mt][nt], ah[mt], bh[nt]);
            }

        if (it + 1 < kIters) {
            unsigned h, l;
            split2(aR0.x, aR0.y, h, l); As_hi[nb][aRow][aCol / 2] = h;     As_lo[nb][aRow][aCol / 2] = l;
            split2(aR0.z, aR0.w, h, l); As_hi[nb][aRow][aCol / 2 + 1] = h; As_lo[nb][aRow][aCol / 2 + 1] = l;
            split2(aR1.x, aR1.y, h, l); As_hi[nb][64 + aRow][aCol / 2] = h;     As_lo[nb][64 + aRow][aCol / 2] = l;
            split2(aR1.z, aR1.w, h, l); As_hi[nb][64 + aRow][aCol / 2 + 1] = h; As_lo[nb][64 + aRow][aCol / 2 + 1] = l;
            split2(bA0.x, bA1.x, h, l); Bs_hi[nb][bCol][bKp] = h;     Bs_lo[nb][bCol][bKp] = l;
            split2(bA0.y, bA1.y, h, l); Bs_hi[nb][bCol + 1][bKp] = h; Bs_lo[nb][bCol + 1][bKp] = l;
            split2(bB0.x, bB1.x, h, l); Bs_hi[nb][bCol][bKp + 4] = h;     Bs_lo[nb][bCol][bKp + 4] = l;
            split2(bB0.y, bB1.y, h, l); Bs_hi[nb][bCol + 1][bKp + 4] = h; Bs_lo[nb][bCol + 1][bKp + 4] = l;
            __syncthreads();
        }
    }

#pragma unroll
    for (int mt = 0; mt < 4; mt++) {
        int r0 = rowBase + warpM * 64 + mt * 16 + lm;
#pragma unroll
        for (int nt = 0; nt < 4; nt++) {
            int col = colBase + warpN * 32 + nt * 8 + lk * 2;
            float bb0 = bias ? bias[col] : 0.f;
            float bb1 = bias ? bias[col + 1] : 0.f;
            float v0 = acc[mt][nt][0] + bb0, v1 = acc[mt][nt][1] + bb1;
            float v2 = acc[mt][nt][2] + bb0, v3 = acc[mt][nt][3] + bb1;
            if (doRelu) {
                v0 = fmaxf(v0, 0.f); v1 = fmaxf(v1, 0.f);
                v2 = fmaxf(v2, 0.f); v3 = fmaxf(v3, 0.f);
            }
            if (r0 < M)     *(float2*)(C + (size_t)r0 * N + col)       = make_float2(v0, v1);
            if (r0 + 8 < M) *(float2*)(C + (size_t)(r0 + 8) * N + col) = make_float2(v2, v3);
        }
    }
}

// ---------------- per-dst GATv2 aggregation (proven R8 version) ----------------
__global__ __launch_bounds__(256) void k_gat_dst(
    const float* __restrict__ xl, const float* __restrict__ xr,
    const float* __restrict__ att, const float* __restrict__ cbias,
    float* __restrict__ hout)
{
    __shared__ float sh_xr[HC];
    __shared__ float sh_out[Hh][Cc];

    int dst = blockIdx.x;
    int tid = threadIdx.x;
    for (int i = tid; i < HC; i += 256) sh_xr[i] = xr[(size_t)dst * HC + i];
    __syncthreads();

    int wid = tid >> 5, lane = tid & 31;
    if (wid < Hh) {
        int h = wid;
        float att0 = att[h * Cc + lane];
        float att1 = att[h * Cc + 32 + lane];
        float xr0 = sh_xr[h * Cc + lane];
        float xr1 = sh_xr[h * Cc + 32 + lane];

        float s = 0.f, a0 = 0.f, a1 = 0.f;
        int beg = g_rowptr[dst], end = g_rowptr[dst + 1];
        const int* csr = g_csr_src;
#pragma unroll 4
        for (int i = beg; i < end; i++) {
            int src = csr[i];
            const float* row = xl + (size_t)src * HC + h * Cc;
            float x0 = row[lane];
            float x1 = row[lane + 32];
            float v0 = x0 + xr0; v0 = (v0 > 0.f) ? v0 : 0.2f * v0;
            float v1 = x1 + xr1; v1 = (v1 > 0.f) ? v1 : 0.2f * v1;
            float p = v0 * att0 + v1 * att1;
#pragma unroll
            for (int o = 16; o; o >>= 1) p += __shfl_xor_sync(0xFFFFFFFFu, p, o);
            float w = __expf(p);
            s  += w;
            a0 += w * x0;
            a1 += w * x1;
        }
        float inv = 1.f / (s + 1e-16f);
        sh_out[h][lane]      = a0 * inv;
        sh_out[h][lane + 32] = a1 * inv;
    }
    __syncthreads();

    if (tid < Cc) {
        float v = 0.f;
#pragma unroll
        for (int h = 0; h < Hh; h++) v += sh_out[h][tid];
        v = v * (1.f / 7.f) + cbias[tid];
        hout[(size_t)dst * Cc + tid] = fmaxf(v, 0.f);
    }
}

// ---------------- fused output MLP + log_softmax ----------------
__global__ __launch_bounds__(128) void k_outmlp(
    const float* __restrict__ h,
    const float* __restrict__ V1, const float* __restrict__ c1,
    const float* __restrict__ V2, const float* __restrict__ c2,
    const float* __restrict__ V3, const float* __restrict__ c3,
    float* __restrict__ out)
{
    __shared__ float sV1[64 * 32], sV2[32 * 16], sV3[16 * 9];
    __shared__ float sc1[32], sc2[16], sc3[9];
    int tid = threadIdx.x;
    for (int i = tid; i < 64 * 32; i += 128) sV1[i] = V1[i];
    for (int i = tid; i < 32 * 16; i += 128) sV2[i] = V2[i];
    for (int i = tid; i < 16 * 9; i += 128)  sV3[i] = V3[i];
    if (tid < 32) sc1[tid] = c1[tid];
    if (tid < 16) sc2[tid] = c2[tid];
    if (tid < 9)  sc3[tid] = c3[tid];
    __syncthreads();

    int row = blockIdx.x * 128 + tid;
    if (row >= Nn) return;

    float x[64];
#pragma unroll
    for (int k = 0; k < 64; k++) x[k] = fmaxf(h[(size_t)row * 64 + k], 0.f);

    float t1[32];
#pragma unroll
    for (int j = 0; j < 32; j++) {
        float v = sc1[j];
#pragma unroll
        for (int k = 0; k < 64; k++) v += x[k] * sV1[k * 32 + j];
        t1[j] = fmaxf(v, 0.f);
    }
    float t2[16];
#pragma unroll
    for (int j = 0; j < 16; j++) {
        float v = sc2[j];
#pragma unroll
        for (int k = 0; k < 32; k++) v += t1[k] * sV2[k * 16 + j];
        t2[j] = fmaxf(v, 0.f);
    }
    float t3[9];
    float mx = -INFINITY;
#pragma unroll
    for (int j = 0; j < 9; j++) {
        float v = sc3[j];
#pragma unroll
        for (int k = 0; k < 16; k++) v += t2[k] * sV3[k * 9 + j];
        t3[j] = v;
        mx = fmaxf(mx, v);
    }
    float se = 0.f;
#pragma unroll
    for (int j = 0; j < 9; j++) se += expf(t3[j] - mx);
    float lse = logf(se) + mx;
#pragma unroll
    for (int j = 0; j < 9; j++) out[(size_t)row * 9 + j] = t3[j] - lse;
}

// ---------------- host ----------------
static void launch_gemm64(const float* A, const float* B, const float* bias,
                          float* C, int M, int N, int K, int relu)
{
    dim3 grid(N / 64, (M + 127) / 128, 1);
    k_bf16gemm<<<grid, 256>>>(A, B, bias, C, B, bias, C, M, N, K, relu);
}
static void launch_gemm128(const float* A, const float* B, const float* bias,
                           float* C, int M, int N, int K, int relu)
{
    dim3 grid(N / 128, (M + 127) / 128, 1);
    k_gemm128<<<grid, 256>>>(A, B, bias, C, M, N, K, relu);
}

extern "C" void kernel_launch(void* const* d_in, const int* in_sizes, int n_in,
                              void* d_out, int out_size)
{
    const float* x  = (const float*)d_in[0];
    const void*  ei = d_in[1];
    const float* W1 = (const float*)d_in[2];  const float* b1 = (const float*)d_in[3];
    const float* W2 = (const float*)d_in[4];  const float* b2 = (const float*)d_in[5];
    const float* W3 = (const float*)d_in[6];  const float* b3 = (const float*)d_in[7];
    const float* Wl = (const float*)d_in[8];  const float* bl = (const float*)d_in[9];
    const float* Wr = (const float*)d_in[10];
    const float* att   = (const float*)d_in[11];
    const float* cbias = (const float*)d_in[12];
    const float* V1 = (const float*)d_in[13]; const float* c1 = (const float*)d_in[14];
    const float* V2 = (const float*)d_in[15]; const float* c2 = (const float*)d_in[16];
    const float* V3 = (const float*)d_in[17]; const float* c3 = (const float*)d_in[18];
    float* out = (float*)d_out;

    float *p_h0, *p_h1, *p_hA, *p_hB, *p_xl, *p_xr;
    cudaGetSymbolAddress((void**)&p_h0, g_h0);
    cudaGetSymbolAddress((void**)&p_h1, g_h1);
    cudaGetSymbolAddress((void**)&p_hA, g_hA);
    cudaGetSymbolAddress((void**)&p_hB, g_hB);
    cudaGetSymbolAddress((void**)&p_xl, g_xl);
    cudaGetSymbolAddress((void**)&p_xr, g_xr);

    k_detect<<<1, 256>>>((const int*)ei);
    k_clear_deg<<<(Nn + 255) / 256, 256>>>();
    k_count<<<(Etot + 255) / 256, 256>>>(ei);
    launch_gemm128(x, W1, b1, p_h0, Nn, 512, 1024, 1);   // independent of CSR
    k_scan<<<1, 1024>>>();
    k_scatter<<<(Etot + 255) / 256, 256>>>(ei);

    launch_gemm128(p_h0, W2, b2, p_h1, Nn, 256, 512, 1);
    launch_gemm64(p_h1, W3, b3, p_hA, Nn, 64, 256, 1);

    float* cur = p_hA;
    float* nxt = p_hB;
    for (int l = 0; l < 5; l++) {
        const float* Wl_l = Wl + (size_t)l * 64 * HC;
        const float* bl_l = bl + (size_t)l * HC;
        const float* Wr_l = Wr + (size_t)l * 64 * HC;
        const float* att_l = att + (size_t)l * Hh * Cc;
        const float* cb_l  = cbias + (size_t)l * Cc;
        dim3 grid(HC / 64, (Nn + 127) / 128, 2);
        k_bf16gemm<<<grid, 256>>>(cur, Wl_l, bl_l, p_xl, Wr_l, nullptr, p_xr,
                                  Nn, HC, 64, 0);
        k_gat_dst<<<Nn, 256>>>(p_xl, p_xr, att_l, cb_l, nxt);
        float* t = cur; cur = nxt; nxt = t;
    }

    k_outmlp<<<(Nn + 127) / 128, 128>>>(cur, V1, c1, V2, c2, V3, c3, out);
}

// round 17
// speedup vs baseline: 1.6834x; 1.0290x over previous
#include <cuda_runtime.h>
#include <math.h>

#define Nn 10000
#define Ee 160000
#define Etot (Ee + Nn)
#define Hh 7
#define Cc 64
#define HC 448

// ---------------- scratch ----------------
__device__ float g_h0[Nn * 512];
__device__ float g_h1[Nn * 256];
__device__ float g_hA[Nn * 64];
__device__ float g_hB[Nn * 64];
__device__ float g_xl[Nn * HC];
__device__ float g_xr[Nn * HC];
__device__ int   g_deg[Nn];
__device__ int   g_rowptr[Nn + 1];
__device__ int   g_wpos[Nn];
__device__ int   g_csr_src[Etot];
__device__ int   g_is64;

// ---------------- edge dtype detection (parallel) ----------------
__global__ void k_detect(const int* __restrict__ ei32) {
    int nz = (ei32[2 * threadIdx.x + 1] != 0) ? 1 : 0;
    int tot = __syncthreads_count(nz);
    if (threadIdx.x == 0) g_is64 = (tot == 0) ? 1 : 0;
}
__device__ __forceinline__ int edge_val(const void* ei, int idx) {
    if (g_is64) return (int)((const long long*)ei)[idx];
    return ((const int*)ei)[idx];
}

// ---------------- CSR build ----------------
__global__ void k_clear_deg() {
    int i = blockIdx.x * blockDim.x + threadIdx.x;
    if (i < Nn) g_deg[i] = 0;
}
__global__ void k_count(const void* __restrict__ ei) {
    int e = blockIdx.x * blockDim.x + threadIdx.x;
    if (e >= Etot) return;
    int dst = (e < Ee) ? edge_val(ei, Ee + e) : (e - Ee);
    if ((unsigned)dst < Nn) atomicAdd(&g_deg[dst], 1);
}

__global__ void k_scan() {
    int t = threadIdx.x;
    int base = t * 10;
    int v[10]; int s = 0;
#pragma unroll
    for (int i = 0; i < 10; i++) {
        int idx = base + i;
        v[i] = (idx < Nn) ? g_deg[idx] : 0;
        s += v[i];
    }
    int lane = t & 31, wid = t >> 5;
    int ss = s;
#pragma unroll
    for (int o = 1; o < 32; o <<= 1) {
        int u = __shfl_up_sync(0xFFFFFFFFu, ss, o);
        if (lane >= o) ss += u;
    }
    __shared__ int wsum[32];
    if (lane == 31) wsum[wid] = ss;
    __syncthreads();
    if (wid == 0) {
        int w = wsum[lane];
#pragma unroll
        for (int o = 1; o < 32; o <<= 1) {
            int u = __shfl_up_sync(0xFFFFFFFFu, w, o);
            if (lane >= o) w += u;
        }
        wsum[lane] = w;
    }
    __syncthreads();
    int excl = ss - s + (wid ? wsum[wid - 1] : 0);
    int run = excl;
#pragma unroll
    for (int i = 0; i < 10; i++) {
        int idx = base + i;
        if (idx < Nn) {
            g_wpos[idx] = run;
            run += v[i];
            g_rowptr[idx + 1] = run;
        }
    }
    if (t == 0) g_rowptr[0] = 0;
}

__global__ void k_scatter(const void* __restrict__ ei) {
    int e = blockIdx.x * blockDim.x + threadIdx.x;
    if (e >= Etot) return;
    int src, dst;
    if (e < Ee) { src = edge_val(ei, e); dst = edge_val(ei, Ee + e); }
    else        { src = dst = e - Ee; }
    if ((unsigned)dst >= Nn || (unsigned)src >= Nn) return;
    int pos = atomicAdd(&g_wpos[dst], 1);
    if ((unsigned)pos < Etot) g_csr_src[pos] = src;
}

// ---------------- bf16x3 helpers ----------------
__device__ __forceinline__ unsigned pack_bf16(float f_even, float f_odd) {
    unsigned r;
    asm("cvt.rn.bf16x2.f32 %0, %1, %2;" : "=r"(r) : "f"(f_odd), "f"(f_even));
    return r;
}
__device__ __forceinline__ void split2(float f0, float f1, unsigned& hi, unsigned& lo) {
    hi = pack_bf16(f0, f1);
    float r0 = f0 - __uint_as_float(hi << 16);
    float r1 = f1 - __uint_as_float(hi & 0xFFFF0000u);
    lo = pack_bf16(r0, r1);
}
__device__ __forceinline__ void mma16(float c[4], const unsigned a[4], const unsigned b[2]) {
    asm("mma.sync.aligned.m16n8k16.row.col.f32.bf16.bf16.f32 "
        "{%0,%1,%2,%3},{%4,%5,%6,%7},{%8,%9},{%0,%1,%2,%3};"
        : "+f"(c[0]), "+f"(c[1]), "+f"(c[2]), "+f"(c[3])
        : "r"(a[0]), "r"(a[1]), "r"(a[2]), "r"(a[3]), "r"(b[0]), "r"(b[1]));
}

// ---------------- BN=64 GEMM, double-buffered smem (W3 + layers) ----------------
__global__ __launch_bounds__(256) void k_bf16gemm(
    const float* __restrict__ A,
    const float* __restrict__ B0, const float* __restrict__ bias0, float* __restrict__ C0,
    const float* __restrict__ B1, const float* __restrict__ bias1, float* __restrict__ C1,
    int M, int N, int K, int doRelu)
{
    const float* B    = (blockIdx.z == 0) ? B0 : B1;
    const float* bias = (blockIdx.z == 0) ? bias0 : bias1;
    float*       C    = (blockIdx.z == 0) ? C0 : C1;

    __shared__ unsigned As_hi[2][128][9], As_lo[2][128][9];
    __shared__ unsigned Bs_hi[2][64][9],  Bs_lo[2][64][9];

    int tid = threadIdx.x;
    int lane = tid & 31, warp = tid >> 5;
    int warpM = warp & 3, warpN = warp >> 2;
    int rowBase = blockIdx.y * 128;
    int colBase = blockIdx.x * 64;
    int lm = lane >> 2, lk = lane & 3;

    float acc[2][4][4];
#pragma unroll
    for (int mt = 0; mt < 2; mt++)
#pragma unroll
        for (int nt = 0; nt < 4; nt++)
#pragma unroll
            for (int i = 0; i < 4; i++) acc[mt][nt][i] = 0.f;

    int aRow = tid >> 2;
    int aCol = (tid & 3) * 4;
    int bKp  = tid >> 5;
    int bCol = (tid & 31) * 2;
    int gr0 = rowBase + aRow, gr1 = rowBase + 64 + aRow;

    int kIters = K >> 4;
    float4 aR0, aR1; float2 bR0, bR1;

    aR0 = (gr0 < M) ? *(const float4*)(A + (size_t)gr0 * K + aCol) : make_float4(0, 0, 0, 0);
    aR1 = (gr1 < M) ? *(const float4*)(A + (size_t)gr1 * K + aCol) : make_float4(0, 0, 0, 0);
    bR0 = *(const float2*)(B + (size_t)(bKp * 2)     * N + colBase + bCol);
    bR1 = *(const float2*)(B + (size_t)(bKp * 2 + 1) * N + colBase + bCol);
    {
        unsigned h, l;
        split2(aR0.x, aR0.y, h, l); As_hi[0][aRow][aCol / 2] = h;     As_lo[0][aRow][aCol / 2] = l;
        split2(aR0.z, aR0.w, h, l); As_hi[0][aRow][aCol / 2 + 1] = h; As_lo[0][aRow][aCol / 2 + 1] = l;
        split2(aR1.x, aR1.y, h, l); As_hi[0][64 + aRow][aCol / 2] = h;     As_lo[0][64 + aRow][aCol / 2] = l;
        split2(aR1.z, aR1.w, h, l); As_hi[0][64 + aRow][aCol / 2 + 1] = h; As_lo[0][64 + aRow][aCol / 2 + 1] = l;
        split2(bR0.x, bR1.x, h, l); Bs_hi[0][bCol][bKp] = h;     Bs_lo[0][bCol][bKp] = l;
        split2(bR0.y, bR1.y, h, l); Bs_hi[0][bCol + 1][bKp] = h; Bs_lo[0][bCol + 1][bKp] = l;
    }
    __syncthreads();

    for (int it = 0; it < kIters; it++) {
        int cb = it & 1, nb = cb ^ 1;
        if (it + 1 < kIters) {
            int k0 = (it + 1) * 16;
            aR0 = (gr0 < M) ? *(const float4*)(A + (size_t)gr0 * K + k0 + aCol) : make_float4(0, 0, 0, 0);
            aR1 = (gr1 < M) ? *(const float4*)(A + (size_t)gr1 * K + k0 + aCol) : make_float4(0, 0, 0, 0);
            bR0 = *(const float2*)(B + (size_t)(k0 + bKp * 2)     * N + colBase + bCol);
            bR1 = *(const float2*)(B + (size_t)(k0 + bKp * 2 + 1) * N + colBase + bCol);
        }

        unsigned ah[2][4], al[2][4], bh[4][2], bl[4][2];
#pragma unroll
        for (int mt = 0; mt < 2; mt++) {
            int rm = warpM * 32 + mt * 16 + lm;
            ah[mt][0] = As_hi[cb][rm][lk];     al[mt][0] = As_lo[cb][rm][lk];
            ah[mt][1] = As_hi[cb][rm + 8][lk]; al[mt][1] = As_lo[cb][rm + 8][lk];
            ah[mt][2] = As_hi[cb][rm][lk + 4];     al[mt][2] = As_lo[cb][rm][lk + 4];
            ah[mt][3] = As_hi[cb][rm + 8][lk + 4]; al[mt][3] = As_lo[cb][rm + 8][lk + 4];
        }
#pragma unroll
        for (int nt = 0; nt < 4; nt++) {
            int cn = warpN * 32 + nt * 8 + lm;
            bh[nt][0] = Bs_hi[cb][cn][lk];     bl[nt][0] = Bs_lo[cb][cn][lk];
            bh[nt][1] = Bs_hi[cb][cn][lk + 4]; bl[nt][1] = Bs_lo[cb][cn][lk + 4];
        }
#pragma unroll
        for (int mt = 0; mt < 2; mt++)
#pragma unroll
            for (int nt = 0; nt < 4; nt++) {
                mma16(acc[mt][nt], ah[mt], bl[nt]);
                mma16(acc[mt][nt], al[mt], bh[nt]);
                mma16(acc[mt][nt], ah[mt], bh[nt]);
            }

        if (it + 1 < kIters) {
            unsigned h, l;
            split2(aR0.x, aR0.y, h, l); As_hi[nb][aRow][aCol / 2] = h;     As_lo[nb][aRow][aCol / 2] = l;
            split2(aR0.z, aR0.w, h, l); As_hi[nb][aRow][aCol / 2 + 1] = h; As_lo[nb][aRow][aCol / 2 + 1] = l;
            split2(aR1.x, aR1.y, h, l); As_hi[nb][64 + aRow][aCol / 2] = h;     As_lo[nb][64 + aRow][aCol / 2] = l;
            split2(aR1.z, aR1.w, h, l); As_hi[nb][64 + aRow][aCol / 2 + 1] = h; As_lo[nb][64 + aRow][aCol / 2 + 1] = l;
            split2(bR0.x, bR1.x, h, l); Bs_hi[nb][bCol][bKp] = h;     Bs_lo[nb][bCol][bKp] = l;
            split2(bR0.y, bR1.y, h, l); Bs_hi[nb][bCol + 1][bKp] = h; Bs_lo[nb][bCol + 1][bKp] = l;
            __syncthreads();
        }
    }

#pragma unroll
    for (int mt = 0; mt < 2; mt++) {
        int r0 = rowBase + warpM * 32 + mt * 16 + lm;
#pragma unroll
        for (int nt = 0; nt < 4; nt++) {
            int col = colBase + warpN * 32 + nt * 8 + lk * 2;
            float bb0 = bias ? bias[col] : 0.f;
            float bb1 = bias ? bias[col + 1] : 0.f;
            float v0 = acc[mt][nt][0] + bb0, v1 = acc[mt][nt][1] + bb1;
            float v2 = acc[mt][nt][2] + bb0, v3 = acc[mt][nt][3] + bb1;
            if (doRelu) {
                v0 = fmaxf(v0, 0.f); v1 = fmaxf(v1, 0.f);
                v2 = fmaxf(v2, 0.f); v3 = fmaxf(v3, 0.f);
            }
            if (r0 < M)     *(float2*)(C + (size_t)r0 * N + col)       = make_float2(v0, v1);
            if (r0 + 8 < M) *(float2*)(C + (size_t)(r0 + 8) * N + col) = make_float2(v2, v3);
        }
    }
}

// ---------------- BN=128 GEMM, warp tile 64x32, double-buffered (W1/W2) ----------------
__global__ __launch_bounds__(256) void k_gemm128(
    const float* __restrict__ A, const float* __restrict__ B,
    const float* __restrict__ bias, float* __restrict__ C,
    int M, int N, int K, int doRelu)
{
    __shared__ unsigned As_hi[2][128][9], As_lo[2][128][9];
    __shared__ unsigned Bs_hi[2][128][9], Bs_lo[2][128][9];

    int tid = threadIdx.x;
    int lane = tid & 31, warp = tid >> 5;
    int warpM = warp >> 2;
    int warpN = warp & 3;
    int rowBase = blockIdx.y * 128;
    int colBase = blockIdx.x * 128;
    int lm = lane >> 2, lk = lane & 3;

    float acc[4][4][4];
#pragma unroll
    for (int mt = 0; mt < 4; mt++)
#pragma unroll
        for (int nt = 0; nt < 4; nt++)
#pragma unroll
            for (int i = 0; i < 4; i++) acc[mt][nt][i] = 0.f;

    int aRow = tid >> 2;
    int aCol = (tid & 3) * 4;
    int bKp  = tid >> 6;
    int bCol = (tid & 63) * 2;
    int gr0 = rowBase + aRow, gr1 = rowBase + 64 + aRow;

    int kIters = K >> 4;
    float4 aR0, aR1;
    float2 bA0, bA1, bB0, bB1;

    aR0 = (gr0 < M) ? *(const float4*)(A + (size_t)gr0 * K + aCol) : make_float4(0, 0, 0, 0);
    aR1 = (gr1 < M) ? *(const float4*)(A + (size_t)gr1 * K + aCol) : make_float4(0, 0, 0, 0);
    {
        const float* bp = B + colBase + bCol;
        bA0 = *(const float2*)(bp + (size_t)(bKp * 2) * N);
        bA1 = *(const float2*)(bp + (size_t)(bKp * 2 + 1) * N);
        bB0 = *(const float2*)(bp + (size_t)((bKp + 4) * 2) * N);
        bB1 = *(const float2*)(bp + (size_t)((bKp + 4) * 2 + 1) * N);
    }
    {
        unsigned h, l;
        split2(aR0.x, aR0.y, h, l); As_hi[0][aRow][aCol / 2] = h;     As_lo[0][aRow][aCol / 2] = l;
        split2(aR0.z, aR0.w, h, l); As_hi[0][aRow][aCol / 2 + 1] = h; As_lo[0][aRow][aCol / 2 + 1] = l;
        split2(aR1.x, aR1.y, h, l); As_hi[0][64 + aRow][aCol / 2] = h;     As_lo[0][64 + aRow][aCol / 2] = l;
        split2(aR1.z, aR1.w, h, l); As_hi[0][64 + aRow][aCol / 2 + 1] = h; As_lo[0][64 + aRow][aCol / 2 + 1] = l;
        split2(bA0.x, bA1.x, h, l); Bs_hi[0][bCol][bKp] = h;     Bs_lo[0][bCol][bKp] = l;
        split2(bA0.y, bA1.y, h, l); Bs_hi[0][bCol + 1][bKp] = h; Bs_lo[0][bCol + 1][bKp] = l;
        split2(bB0.x, bB1.x, h, l); Bs_hi[0][bCol][bKp + 4] = h;     Bs_lo[0][bCol][bKp + 4] = l;
        split2(bB0.y, bB1.y, h, l); Bs_hi[0][bCol + 1][bKp + 4] = h; Bs_lo[0][bCol + 1][bKp + 4] = l;
    }
    __syncthreads();

    for (int it = 0; it < kIters; it++) {
        int cb = it & 1, nb = cb ^ 1;
        if (it + 1 < kIters) {
            int k0 = (it + 1) * 16;
            aR0 = (gr0 < M) ? *(const float4*)(A + (size_t)gr0 * K + k0 + aCol) : make_float4(0, 0, 0, 0);
            aR1 = (gr1 < M) ? *(const float4*)(A + (size_t)gr1 * K + k0 + aCol) : make_float4(0, 0, 0, 0);
            const float* bp = B + colBase + bCol;
            bA0 = *(const float2*)(bp + (size_t)(k0 + bKp * 2) * N);
            bA1 = *(const float2*)(bp + (size_t)(k0 + bKp * 2 + 1) * N);
            bB0 = *(const float2*)(bp + (size_t)(k0 + (bKp + 4) * 2) * N);
            bB1 = *(const float2*)(bp + (size_t)(k0 + (bKp + 4) * 2 + 1) * N);
        }

        unsigned ah[4][4], al[4][4], bh[4][2], bl[4][2];
#pragma unroll
        for (int mt = 0; mt < 4; mt++) {
            int rm = warpM * 64 + mt * 16 + lm;
            ah[mt][0] = As_hi[cb][rm][lk];     al[mt][0] = As_lo[cb][rm][lk];
            ah[mt][1] = As_hi[cb][rm + 8][lk]; al[mt][1] = As_lo[cb][rm + 8][lk];
            ah[mt][2] = As_hi[cb][rm][lk + 4];     al[mt][2] = As_lo[cb][rm][lk + 4];
            ah[mt][3] = As_hi[cb][rm + 8][lk + 4]; al[mt][3] = As_lo[cb][rm + 8][lk + 4];
        }
#pragma unroll
        for (int nt = 0; nt < 4; nt++) {
            int cn = warpN * 32 + nt * 8 + lm;
            bh[nt][0] = Bs_hi[cb][cn][lk];     bl[nt][0] = Bs_lo[cb][cn][lk];
            bh[nt][1] = Bs_hi[cb][cn][lk + 4]; bl[nt][1] = Bs_lo[cb][cn][lk + 4];
        }
#pragma unroll
        for (int mt = 0; mt < 4; mt++)
#pragma unroll
            for (int nt = 0; nt < 4; nt++) {
                mma16(acc[mt][nt], ah[mt], bl[nt]);
                mma16(acc[mt][nt], al[mt], bh[nt]);
                mma16(acc[mt][nt], ah[mt], bh[nt]);
            }

        if (it + 1 < kIters) {
            unsigned h, l;
            split2(aR0.x, aR0.y, h, l); As_hi[nb][aRow][aCol / 2] = h;     As_lo[nb][aRow][aCol / 2] = l;
            split2(aR0.z, aR0.w, h, l); As_hi[nb][aRow][aCol / 2 + 1] = h; As_lo[nb][aRow][aCol / 2 + 1] = l;
            split2(aR1.x, aR1.y, h, l); As_hi[nb][64 + aRow][aCol / 2] = h;     As_lo[nb][64 + aRow][aCol / 2] = l;
            split2(aR1.z, aR1.w, h, l); As_hi[nb][64 + aRow][aCol / 2 + 1] = h; As_lo[nb][64 + aRow][aCol / 2 + 1] = l;
            split2(bA0.x, bA1.x, h, l); Bs_hi[nb][bCol][bKp] = h;     Bs_lo[nb][bCol][bKp] = l;
            split2(bA0.y, bA1.y, h, l); Bs_hi[nb][bCol + 1][bKp] = h; Bs_lo[nb][bCol + 1][bKp] = l;
            split2(bB0.x, bB1.x, h, l); Bs_hi[nb][bCol][bKp + 4] = h;     Bs_lo[nb][bCol][bKp + 4] = l;
            split2(bB0.y, bB1.y, h, l); Bs_hi[nb][bCol + 1][bKp + 4] = h; Bs_lo[nb][bCol + 1][bKp + 4] = l;
            __syncthreads();
        }
    }

#pragma unroll
    for (int mt = 0; mt < 4; mt++) {
        int r0 = rowBase + warpM * 64 + mt * 16 + lm;
#pragma unroll
        for (int nt = 0; nt < 4; nt++) {
            int col = colBase + warpN * 32 + nt * 8 + lk * 2;
            float bb0 = bias ? bias[col] : 0.f;
            float bb1 = bias ? bias[col + 1] : 0.f;
            float v0 = acc[mt][nt][0] + bb0, v1 = acc[mt][nt][1] + bb1;
            float v2 = acc[mt][nt][2] + bb0, v3 = acc[mt][nt][3] + bb1;
            if (doRelu) {
                v0 = fmaxf(v0, 0.f); v1 = fmaxf(v1, 0.f);
                v2 = fmaxf(v2, 0.f); v3 = fmaxf(v3, 0.f);
            }
            if (r0 < M)     *(float2*)(C + (size_t)r0 * N + col)       = make_float2(v0, v1);
            if (r0 + 8 < M) *(float2*)(C + (size_t)(r0 + 8) * N + col) = make_float2(v2, v3);
        }
    }
}

// ---------------- per-dst GATv2 aggregation (proven R8 version) ----------------
__global__ __launch_bounds__(256) void k_gat_dst(
    const float* __restrict__ xl, const float* __restrict__ xr,
    const float* __restrict__ att, const float* __restrict__ cbias,
    float* __restrict__ hout)
{
    __shared__ float sh_xr[HC];
    __shared__ float sh_out[Hh][Cc];

    int dst = blockIdx.x;
    int tid = threadIdx.x;
    for (int i = tid; i < HC; i += 256) sh_xr[i] = xr[(size_t)dst * HC + i];
    __syncthreads();

    int wid = tid >> 5, lane = tid & 31;
    if (wid < Hh) {
        int h = wid;
        float att0 = att[h * Cc + lane];
        float att1 = att[h * Cc + 32 + lane];
        float xr0 = sh_xr[h * Cc + lane];
        float xr1 = sh_xr[h * Cc + 32 + lane];

        float s = 0.f, a0 = 0.f, a1 = 0.f;
        int beg = g_rowptr[dst], end = g_rowptr[dst + 1];
        const int* csr = g_csr_src;
#pragma unroll 4
        for (int i = beg; i < end; i++) {
            int src = csr[i];
            const float* row = xl + (size_t)src * HC + h * Cc;
            float x0 = row[lane];
            float x1 = row[lane + 32];
            float v0 = x0 + xr0; v0 = (v0 > 0.f) ? v0 : 0.2f * v0;
            float v1 = x1 + xr1; v1 = (v1 > 0.f) ? v1 : 0.2f * v1;
            float p = v0 * att0 + v1 * att1;
#pragma unroll
            for (int o = 16; o; o >>= 1) p += __shfl_xor_sync(0xFFFFFFFFu, p, o);
            float w = __expf(p);
            s  += w;
            a0 += w * x0;
            a1 += w * x1;
        }
        float inv = 1.f / (s + 1e-16f);
        sh_out[h][lane]      = a0 * inv;
        sh_out[h][lane + 32] = a1 * inv;
    }
    __syncthreads();

    if (tid < Cc) {
        float v = 0.f;
#pragma unroll
        for (int h = 0; h < Hh; h++) v += sh_out[h][tid];
        v = v * (1.f / 7.f) + cbias[tid];
        hout[(size_t)dst * Cc + tid] = fmaxf(v, 0.f);
    }
}

// ---------------- fused output MLP + log_softmax ----------------
__global__ __launch_bounds__(128) void k_outmlp(
    const float* __restrict__ h,
    const float* __restrict__ V1, const float* __restrict__ c1,
    const float* __restrict__ V2, const float* __restrict__ c2,
    const float* __restrict__ V3, const float* __restrict__ c3,
    float* __restrict__ out)
{
    __shared__ float sV1[64 * 32], sV2[32 * 16], sV3[16 * 9];
    __shared__ float sc1[32], sc2[16], sc3[9];
    int tid = threadIdx.x;
    for (int i = tid; i < 64 * 32; i += 128) sV1[i] = V1[i];
    for (int i = tid; i < 32 * 16; i += 128) sV2[i] = V2[i];
    for (int i = tid; i < 16 * 9; i += 128)  sV3[i] = V3[i];
    if (tid < 32) sc1[tid] = c1[tid];
    if (tid < 16) sc2[tid] = c2[tid];
    if (tid < 9)  sc3[tid] = c3[tid];
    __syncthreads();

    int row = blockIdx.x * 128 + tid;
    if (row >= Nn) return;

    float x[64];
#pragma unroll
    for (int k = 0; k < 64; k++) x[k] = fmaxf(h[(size_t)row * 64 + k], 0.f);

    float t1[32];
#pragma unroll
    for (int j = 0; j < 32; j++) {
        float v = sc1[j];
#pragma unroll
        for (int k = 0; k < 64; k++) v += x[k] * sV1[k * 32 + j];
        t1[j] = fmaxf(v, 0.f);
    }
    float t2[16];
#pragma unroll
    for (int j = 0; j < 16; j++) {
        float v = sc2[j];
#pragma unroll
        for (int k = 0; k < 32; k++) v += t1[k] * sV2[k * 16 + j];
        t2[j] = fmaxf(v, 0.f);
    }
    float t3[9];
    float mx = -INFINITY;
#pragma unroll
    for (int j = 0; j < 9; j++) {
        float v = sc3[j];
#pragma unroll
        for (int k = 0; k < 16; k++) v += t2[k] * sV3[k * 9 + j];
        t3[j] = v;
        mx = fmaxf(mx, v);
    }
    float se = 0.f;
#pragma unroll
    for (int j = 0; j < 9; j++) se += expf(t3[j] - mx);
    float lse = logf(se) + mx;
#pragma unroll
    for (int j = 0; j < 9; j++) out[(size_t)row * 9 + j] = t3[j] - lse;
}

// ---------------- host ----------------
static void launch_gemm64(const float* A, const float* B, const float* bias,
                          float* C, int M, int N, int K, int relu)
{
    dim3 grid(N / 64, (M + 127) / 128, 1);
    k_bf16gemm<<<grid, 256>>>(A, B, bias, C, B, bias, C, M, N, K, relu);
}
static void launch_gemm128(const float* A, const float* B, const float* bias,
                           float* C, int M, int N, int K, int relu)
{
    dim3 grid(N / 128, (M + 127) / 128, 1);
    k_gemm128<<<grid, 256>>>(A, B, bias, C, M, N, K, relu);
}

extern "C" void kernel_launch(void* const* d_in, const int* in_sizes, int n_in,
                              void* d_out, int out_size)
{
    const float* x  = (const float*)d_in[0];
    const void*  ei = d_in[1];
    const float* W1 = (const float*)d_in[2];  const float* b1 = (const float*)d_in[3];
    const float* W2 = (const float*)d_in[4];  const float* b2 = (const float*)d_in[5];
    const float* W3 = (const float*)d_in[6];  const float* b3 = (const float*)d_in[7];
    const float* Wl = (const float*)d_in[8];  const float* bl = (const float*)d_in[9];
    const float* Wr = (const float*)d_in[10];
    const float* att   = (const float*)d_in[11];
    const float* cbias = (const float*)d_in[12];
    const float* V1 = (const float*)d_in[13]; const float* c1 = (const float*)d_in[14];
    const float* V2 = (const float*)d_in[15]; const float* c2 = (const float*)d_in[16];
    const float* V3 = (const float*)d_in[17]; const float* c3 = (const float*)d_in[18];
    float* out = (float*)d_out;

    float *p_h0, *p_h1, *p_hA, *p_hB, *p_xl, *p_xr;
    cudaGetSymbolAddress((void**)&p_h0, g_h0);
    cudaGetSymbolAddress((void**)&p_h1, g_h1);
    cudaGetSymbolAddress((void**)&p_hA, g_hA);
    cudaGetSymbolAddress((void**)&p_hB, g_hB);
    cudaGetSymbolAddress((void**)&p_xl, g_xl);
    cudaGetSymbolAddress((void**)&p_xr, g_xr);

    // lazily-created side stream + events (one-time; not allocations in the graph)
    static cudaStream_t s_side = 0;
    static cudaEvent_t ev_fork = 0, ev_join = 0;
    if (!s_side) {
        cudaStreamCreateWithFlags(&s_side, cudaStreamNonBlocking);
        cudaEventCreateWithFlags(&ev_fork, cudaEventDisableTiming);
        cudaEventCreateWithFlags(&ev_join, cudaEventDisableTiming);
    }

    // fork: CSR build runs on side stream, concurrent with the input MLP
    cudaEventRecord(ev_fork, 0);
    cudaStreamWaitEvent(s_side, ev_fork, 0);

    k_detect<<<1, 256, 0, s_side>>>((const int*)ei);
    k_clear_deg<<<(Nn + 255) / 256, 256, 0, s_side>>>();
    k_count<<<(Etot + 255) / 256, 256, 0, s_side>>>(ei);
    k_scan<<<1, 1024, 0, s_side>>>();
    k_scatter<<<(Etot + 255) / 256, 256, 0, s_side>>>(ei);
    cudaEventRecord(ev_join, s_side);

    // main stream: input MLP (does not depend on CSR)
    launch_gemm128(x, W1, b1, p_h0, Nn, 512, 1024, 1);
    launch_gemm128(p_h0, W2, b2, p_h1, Nn, 256, 512, 1);
    launch_gemm64(p_h1, W3, b3, p_hA, Nn, 64, 256, 1);

    float* cur = p_hA;
    float* nxt = p_hB;
    for (int l = 0; l < 5; l++) {
        const float* Wl_l = Wl + (size_t)l * 64 * HC;
        const float* bl_l = bl + (size_t)l * HC;
        const float* Wr_l = Wr + (size_t)l * 64 * HC;
        const float* att_l = att + (size_t)l * Hh * Cc;
        const float* cb_l  = cbias + (size_t)l * Cc;
        dim3 grid(HC / 64, (Nn + 127) / 128, 2);
        k_bf16gemm<<<grid, 256>>>(cur, Wl_l, bl_l, p_xl, Wr_l, nullptr, p_xr,
                                  Nn, HC, 64, 0);
        if (l == 0) cudaStreamWaitEvent(0, ev_join, 0);   // join before first CSR consumer
        k_gat_dst<<<Nn, 256>>>(p_xl, p_xr, att_l, cb_l, nxt);
        float* t = cur; cur = nxt; nxt = t;
    }

    k_outmlp<<<(Nn + 127) / 128, 128>>>(cur, V1, c1, V2, c2, V3, c3, out);
}